// round 3
// baseline (speedup 1.0000x reference)
#include <cuda_runtime.h>
#include <math.h>

// ---------------- scratch (static device globals; no allocation) ----------------
__device__ float g_h1[16777216];   // (1024, 16, 16, 64)   conv1+LN+GELU out, 67MB
__device__ float g_h2[4194304];    // (1024, 4, 4, 256) -> (1024, 4096)        16.8MB
__device__ float g_emb[524288];    // (1024, 512)
__device__ float g_w1r[16384];     // conv1 weights rearranged (k=256, cout=64)
__device__ float g_w2r[262144];    // conv2 weights rearranged (k=1024, cout=256)
__device__ float g_gates[384];     // (64, 6) dense gates

// ---------------- weight rearrangement ----------------
// conv1 patch k = kh*64 + kw*16 + cin ; conv2 patch k = kh*256 + kw*64 + cin
__global__ void prep_kernel(const float* __restrict__ w1, const float* __restrict__ w2) {
    int idx = blockIdx.x * 256 + threadIdx.x;
    if (idx < 16384) {
        int k = idx >> 6, c = idx & 63;
        int kh = k >> 6, kw = (k >> 4) & 3, ci = k & 15;
        g_w1r[idx] = w1[c * 256 + ci * 16 + kh * 4 + kw];
    }
    if (idx < 262144) {
        int k = idx >> 8, co = idx & 255;
        int kh = k >> 8, kw = (k >> 6) & 3, ci = k & 63;
        g_w2r[idx] = w2[co * 1024 + ci * 16 + kh * 4 + kw];
    }
}

__device__ __forceinline__ float gelu_exact(float y) {
    return 0.5f * y * (1.f + erff(y * 0.70710678118654752440f));
}

// ---------------- conv1 (patchify GEMM M=262144,K=256,N=64) + LN + GELU ----------------
// block: 128 rows x 64 cols, 256 threads, micro 8x4
__global__ __launch_bounds__(256) void conv1_kernel(
    const float* __restrict__ x, const float* __restrict__ cb,
    const float* __restrict__ lg, const float* __restrict__ lb) {
    __shared__ float As[16][128];
    __shared__ float Bs[16][64];
    __shared__ float rs[128][16];
    __shared__ float rq[128][16];
    const int tid = threadIdx.x;
    const int tx = tid & 15, ty = tid >> 4;
    const int m0 = blockIdx.x * 128;
    float acc[8][4];
#pragma unroll
    for (int r = 0; r < 8; r++)
#pragma unroll
        for (int c = 0; c < 4; c++) acc[r][c] = 0.f;

    for (int kc = 0; kc < 256; kc += 16) {
#pragma unroll
        for (int q = 0; q < 2; q++) {
            int gI = tid * 2 + q;
            int ml = gI >> 2;
            int k4 = (gI & 3) * 4;
            int m = m0 + ml;
            int bt = m >> 8, ij = m & 255, i = ij >> 4, j = ij & 15;
            int k = kc + k4;
            int kh = k >> 6, ko = k & 63;
            float4 v = *(const float4*)&x[bt * 65536 + (4 * i + kh) * 1024 + j * 64 + ko];
            As[k4 + 0][ml] = v.x; As[k4 + 1][ml] = v.y;
            As[k4 + 2][ml] = v.z; As[k4 + 3][ml] = v.w;
        }
        {
            int kl = tid >> 4, n4 = (tid & 15) * 4;
            *(float4*)&Bs[kl][n4] = *(const float4*)&g_w1r[(kc + kl) * 64 + n4];
        }
        __syncthreads();
#pragma unroll
        for (int k = 0; k < 16; k++) {
            float4 a0 = *(const float4*)&As[k][ty * 8];
            float4 a1 = *(const float4*)&As[k][ty * 8 + 4];
            float4 bv = *(const float4*)&Bs[k][tx * 4];
            float a[8] = {a0.x, a0.y, a0.z, a0.w, a1.x, a1.y, a1.z, a1.w};
            float bb[4] = {bv.x, bv.y, bv.z, bv.w};
#pragma unroll
            for (int r = 0; r < 8; r++)
#pragma unroll
                for (int c = 0; c < 4; c++) acc[r][c] = fmaf(a[r], bb[c], acc[r][c]);
        }
        __syncthreads();
    }
    // bias + LN partials
#pragma unroll
    for (int r = 0; r < 8; r++) {
        float s = 0.f, s2 = 0.f;
#pragma unroll
        for (int c = 0; c < 4; c++) {
            acc[r][c] += cb[tx * 4 + c];
            s += acc[r][c];
            s2 += acc[r][c] * acc[r][c];
        }
        rs[ty * 8 + r][tx] = s;
        rq[ty * 8 + r][tx] = s2;
    }
    __syncthreads();
#pragma unroll
    for (int r = 0; r < 8; r++) {
        int row = ty * 8 + r;
        float s = 0.f, s2 = 0.f;
#pragma unroll
        for (int t = 0; t < 16; t++) { s += rs[row][t]; s2 += rq[row][t]; }
        float mean = s * (1.f / 64.f);
        float var = s2 * (1.f / 64.f) - mean * mean;
        float inv = rsqrtf(var + 1e-5f);
        int m = m0 + row;
        float4 o;
        float* po = &o.x;
#pragma unroll
        for (int c = 0; c < 4; c++) {
            int col = tx * 4 + c;
            float y = (acc[r][c] - mean) * inv * lg[col] + lb[col];
            po[c] = gelu_exact(y);
        }
        *(float4*)&g_h1[m * 64 + tx * 4] = o;
    }
}

// ---------------- conv2 (patchify GEMM M=16384,K=1024,N=256) + LN + GELU ----------------
// block: 64 rows x 256 cols, 256 threads, micro 8x8
__global__ __launch_bounds__(256) void conv2_kernel(
    const float* __restrict__ cb, const float* __restrict__ lg, const float* __restrict__ lb) {
    __shared__ float As[16][64];
    __shared__ float Bs[16][256];
    __shared__ float rs[64][32];
    __shared__ float rq[64][32];
    const int tid = threadIdx.x;
    const int tx = tid & 31, ty = tid >> 5;
    const int m0 = blockIdx.x * 64;
    float acc[8][8];
#pragma unroll
    for (int r = 0; r < 8; r++)
#pragma unroll
        for (int c = 0; c < 8; c++) acc[r][c] = 0.f;

    for (int kc = 0; kc < 1024; kc += 16) {
        {
            int ml = tid >> 2, k4 = (tid & 3) * 4;
            int m = m0 + ml;
            int bt = m >> 4, ij = m & 15, oi = ij >> 2, oj = ij & 3;
            int k = kc + k4;
            int kh = k >> 8, ko = k & 255;
            float4 v = *(const float4*)&g_h1[bt * 16384 + (4 * oi + kh) * 1024 + oj * 256 + ko];
            As[k4 + 0][ml] = v.x; As[k4 + 1][ml] = v.y;
            As[k4 + 2][ml] = v.z; As[k4 + 3][ml] = v.w;
        }
#pragma unroll
        for (int q = 0; q < 4; q++) {
            int vI = tid + q * 256;
            int kl = vI >> 6, n4 = (vI & 63) * 4;
            *(float4*)&Bs[kl][n4] = *(const float4*)&g_w2r[(kc + kl) * 256 + n4];
        }
        __syncthreads();
#pragma unroll
        for (int k = 0; k < 16; k++) {
            float4 a0 = *(const float4*)&As[k][ty * 8];
            float4 a1 = *(const float4*)&As[k][ty * 8 + 4];
            float4 b0 = *(const float4*)&Bs[k][tx * 8];
            float4 b1 = *(const float4*)&Bs[k][tx * 8 + 4];
            float a[8] = {a0.x, a0.y, a0.z, a0.w, a1.x, a1.y, a1.z, a1.w};
            float bb[8] = {b0.x, b0.y, b0.z, b0.w, b1.x, b1.y, b1.z, b1.w};
#pragma unroll
            for (int r = 0; r < 8; r++)
#pragma unroll
                for (int c = 0; c < 8; c++) acc[r][c] = fmaf(a[r], bb[c], acc[r][c]);
        }
        __syncthreads();
    }
#pragma unroll
    for (int r = 0; r < 8; r++) {
        float s = 0.f, s2 = 0.f;
#pragma unroll
        for (int c = 0; c < 8; c++) {
            acc[r][c] += cb[tx * 8 + c];
            s += acc[r][c];
            s2 += acc[r][c] * acc[r][c];
        }
        rs[ty * 8 + r][tx] = s;
        rq[ty * 8 + r][tx] = s2;
    }
    __syncthreads();
#pragma unroll
    for (int r = 0; r < 8; r++) {
        int row = ty * 8 + r;
        float s = 0.f, s2 = 0.f;
#pragma unroll
        for (int t = 0; t < 32; t++) { s += rs[row][t]; s2 += rq[row][t]; }
        float mean = s * (1.f / 256.f);
        float var = s2 * (1.f / 256.f) - mean * mean;
        float inv = rsqrtf(var + 1e-5f);
        int m = m0 + row;
        float4 o0, o1;
        float* p0 = &o0.x; float* p1 = &o1.x;
#pragma unroll
        for (int c = 0; c < 4; c++) {
            int col = tx * 8 + c;
            float y = (acc[r][c] - mean) * inv * lg[col] + lb[col];
            p0[c] = gelu_exact(y);
        }
#pragma unroll
        for (int c = 4; c < 8; c++) {
            int col = tx * 8 + c;
            float y = (acc[r][c] - mean) * inv * lg[col] + lb[col];
            p1[c - 4] = gelu_exact(y);
        }
        *(float4*)&g_h2[m * 256 + tx * 8] = o0;
        *(float4*)&g_h2[m * 256 + tx * 8 + 4] = o1;
    }
}

// ---------------- fc GEMM (M=1024,K=4096,N=512) + bias ----------------
// block 64x64, 256 threads, micro 4x4; grid (N/64, M/64)
__global__ __launch_bounds__(256) void fc_kernel(
    const float* __restrict__ fw, const float* __restrict__ fb) {
    __shared__ float As[16][64];
    __shared__ float Bs[16][64];
    const int tid = threadIdx.x;
    const int tx = tid & 15, ty = tid >> 4;
    const int m0 = blockIdx.y * 64, n0 = blockIdx.x * 64;
    float acc[4][4];
#pragma unroll
    for (int r = 0; r < 4; r++)
#pragma unroll
        for (int c = 0; c < 4; c++) acc[r][c] = 0.f;

    for (int kc = 0; kc < 4096; kc += 16) {
        {
            int ml = tid >> 2, k4 = (tid & 3) * 4;
            float4 v = *(const float4*)&g_h2[(m0 + ml) * 4096 + kc + k4];
            As[k4 + 0][ml] = v.x; As[k4 + 1][ml] = v.y;
            As[k4 + 2][ml] = v.z; As[k4 + 3][ml] = v.w;
        }
        {
            int kl = tid >> 4, n4 = (tid & 15) * 4;
            *(float4*)&Bs[kl][n4] = *(const float4*)&fw[(kc + kl) * 512 + n0 + n4];
        }
        __syncthreads();
#pragma unroll
        for (int k = 0; k < 16; k++) {
            float4 av = *(const float4*)&As[k][ty * 4];
            float4 bv = *(const float4*)&Bs[k][tx * 4];
            float a[4] = {av.x, av.y, av.z, av.w};
            float bb[4] = {bv.x, bv.y, bv.z, bv.w};
#pragma unroll
            for (int r = 0; r < 4; r++)
#pragma unroll
                for (int c = 0; c < 4; c++) acc[r][c] = fmaf(a[r], bb[c], acc[r][c]);
        }
        __syncthreads();
    }
#pragma unroll
    for (int r = 0; r < 4; r++) {
        float4 o;
        float* po = &o.x;
#pragma unroll
        for (int c = 0; c < 4; c++) po[c] = acc[r][c] + fb[n0 + tx * 4 + c];
        *(float4*)&g_emb[(m0 + ty * 4 + r) * 512 + n0 + tx * 4] = o;
    }
}

// ---------------- Fourier gating: one block per batch row ----------------
__global__ __launch_bounds__(128) void gate_kernel(const float* __restrict__ w_gate) {
    const int b = blockIdx.x;
    const int tid = threadIdx.x;
    __shared__ float cs[8][16], sn[8][16];
    __shared__ float lgs[6];
    {
        int f = tid >> 4, t = tid & 15;
        float ang = -6.28318530717958647692f * (float)(f + 1) * (float)t * (1.f / 16.f);
        cs[f][t] = cosf(ang);
        sn[f][t] = sinf(ang);
    }
    if (tid < 6) lgs[tid] = 0.f;
    __syncthreads();
    float part[6] = {0.f, 0.f, 0.f, 0.f, 0.f, 0.f};
    for (int d = tid; d < 512; d += 128) {
        float v[16];
#pragma unroll
        for (int t = 0; t < 16; t++) v[t] = g_emb[(b * 16 + t) * 512 + d];
#pragma unroll
        for (int f = 0; f < 8; f++) {
            float re = 0.f, im = 0.f;
#pragma unroll
            for (int t = 0; t < 16; t++) {
                re = fmaf(v[t], cs[f][t], re);
                im = fmaf(v[t], sn[f][t], im);
            }
            float amp = sqrtf(re * re + im * im) * 0.25f;  // ortho norm 1/sqrt(16)
#pragma unroll
            for (int e = 0; e < 6; e++) part[e] = fmaf(amp, w_gate[f * 6 + e], part[e]);
        }
    }
#pragma unroll
    for (int e = 0; e < 6; e++) atomicAdd(&lgs[e], part[e]);
    __syncthreads();
    if (tid == 0) {
        float w[6];
#pragma unroll
        for (int e = 0; e < 6; e++) w[e] = lgs[e] * (1.f / 512.f);
        int i1 = 0;
        for (int e = 1; e < 6; e++) if (w[e] > w[i1]) i1 = e;
        int i2 = -1;
        for (int e = 0; e < 6; e++) {
            if (e == i1) continue;
            if (i2 < 0 || w[e] > w[i2]) i2 = e;
        }
        float e2 = expf(w[i2] - w[i1]);
        float s = 1.f + e2;
#pragma unroll
        for (int e = 0; e < 6; e++) g_gates[b * 6 + e] = 0.f;
        g_gates[b * 6 + i1] = 1.f / s;
        g_gates[b * 6 + i2] = e2 / s;
    }
}

// ---------------- experts (routed top-2) + exp/sum/log combine ----------------
// grid (4 ftiles, 64 b); block 256 threads: 16 rows(t) x 16 colgroups(8 cols)
__global__ __launch_bounds__(256) void expert_kernel(
    const float* __restrict__ ew, const float* __restrict__ eb, float* __restrict__ out) {
    __shared__ float As[32][16];
    __shared__ float Bs[32][128];
    const int tid = threadIdx.x;
    const int tx = tid & 15, ty = tid >> 4;
    const int b = blockIdx.y;
    const int fx = blockIdx.x * 128;
    float comb[8];
#pragma unroll
    for (int c = 0; c < 8; c++) comb[c] = 0.f;

    for (int e = 0; e < 6; e++) {
        float gv = g_gates[b * 6 + e];
        if (gv == 0.f) continue;   // uniform per block
        float acc[8];
#pragma unroll
        for (int c = 0; c < 8; c++) acc[c] = 0.f;
        for (int kc = 0; kc < 512; kc += 32) {
            if (tid < 128) {
                int ml = tid >> 3, k4 = (tid & 7) * 4;
                float4 v = *(const float4*)&g_emb[(b * 16 + ml) * 512 + kc + k4];
                As[k4 + 0][ml] = v.x; As[k4 + 1][ml] = v.y;
                As[k4 + 2][ml] = v.z; As[k4 + 3][ml] = v.w;
            }
#pragma unroll
            for (int q = 0; q < 4; q++) {
                int vI = tid + q * 256;
                int kl = vI >> 5, n4 = (vI & 31) * 4;
                *(float4*)&Bs[kl][n4] = *(const float4*)&ew[(e * 512 + kc + kl) * 512 + fx + n4];
            }
            __syncthreads();
#pragma unroll
            for (int k = 0; k < 32; k++) {
                float a = As[k][ty];
                float4 b0 = *(const float4*)&Bs[k][tx * 8];
                float4 b1 = *(const float4*)&Bs[k][tx * 8 + 4];
                acc[0] = fmaf(a, b0.x, acc[0]);
                acc[1] = fmaf(a, b0.y, acc[1]);
                acc[2] = fmaf(a, b0.z, acc[2]);
                acc[3] = fmaf(a, b0.w, acc[3]);
                acc[4] = fmaf(a, b1.x, acc[4]);
                acc[5] = fmaf(a, b1.y, acc[5]);
                acc[6] = fmaf(a, b1.z, acc[6]);
                acc[7] = fmaf(a, b1.w, acc[7]);
            }
            __syncthreads();
        }
#pragma unroll
        for (int c = 0; c < 8; c++) {
            float z = acc[c] + eb[e * 512 + fx + tx * 8 + c];
            comb[c] = fmaf(gv, expf(z), comb[c]);
        }
    }
#pragma unroll
    for (int c = 0; c < 8; c++) {
        float v = comb[c];
        if (v == 0.f) v = 2.220446049250313e-16f;
        out[(b * 16 + ty) * 512 + fx + tx * 8 + c] = logf(v);
    }
}

// ---------------- launch ----------------
extern "C" void kernel_launch(void* const* d_in, const int* in_sizes, int n_in,
                              void* d_out, int out_size) {
    const float* x       = (const float*)d_in[0];
    const float* conv1_w = (const float*)d_in[1];
    const float* conv1_b = (const float*)d_in[2];
    const float* ln1_g   = (const float*)d_in[3];
    const float* ln1_b   = (const float*)d_in[4];
    const float* conv2_w = (const float*)d_in[5];
    const float* conv2_b = (const float*)d_in[6];
    const float* ln2_g   = (const float*)d_in[7];
    const float* ln2_b   = (const float*)d_in[8];
    const float* fc_w    = (const float*)d_in[9];
    const float* fc_b    = (const float*)d_in[10];
    const float* w_gate  = (const float*)d_in[11];
    const float* exp_w   = (const float*)d_in[12];
    const float* exp_b   = (const float*)d_in[13];
    float* out = (float*)d_out;

    prep_kernel<<<1024, 256>>>(conv1_w, conv2_w);
    conv1_kernel<<<2048, 256>>>(x, conv1_b, ln1_g, ln1_b);
    conv2_kernel<<<256, 256>>>(conv2_b, ln2_g, ln2_b);
    fc_kernel<<<dim3(8, 16), 256>>>(fc_w, fc_b);
    gate_kernel<<<64, 128>>>(w_gate);
    expert_kernel<<<dim3(4, 64), 256>>>(exp_w, exp_b, out);
}

// round 4
// speedup vs baseline: 1.0502x; 1.0502x over previous
#include <cuda_runtime.h>
#include <math.h>

// ---------------- scratch (static device globals; no allocation) ----------------
__device__ float g_h1[16777216];   // (1024, 16, 16, 64)   conv1+LN+GELU out, 67MB
__device__ float g_h2[4194304];    // (1024, 4, 4, 256) -> (1024, 4096)        16.8MB
__device__ float g_emb[524288];    // (1024, 512)
__device__ float g_w1r[16384];     // conv1 weights rearranged (k=256, cout=64)
__device__ float g_w2r[262144];    // conv2 weights rearranged (k=1024, cout=256)
__device__ float g_gates[384];     // (64, 6) dense gates

// ---------------- weight rearrangement ----------------
// conv1 patch k = kh*64 + kw*16 + cin ; conv2 patch k = kh*256 + kw*64 + cin
__global__ void prep_kernel(const float* __restrict__ w1, const float* __restrict__ w2) {
    int idx = blockIdx.x * 256 + threadIdx.x;
    if (idx < 16384) {
        int k = idx >> 6, c = idx & 63;
        int kh = k >> 6, kw = (k >> 4) & 3, ci = k & 15;
        g_w1r[idx] = w1[c * 256 + ci * 16 + kh * 4 + kw];
    }
    if (idx < 262144) {
        int k = idx >> 8, co = idx & 255;
        int kh = k >> 8, kw = (k >> 6) & 3, ci = k & 63;
        g_w2r[idx] = w2[co * 1024 + ci * 16 + kh * 4 + kw];
    }
}

__device__ __forceinline__ float gelu_exact(float y) {
    return 0.5f * y * (1.f + erff(y * 0.70710678118654752440f));
}

// ---------------- conv1 (patchify GEMM M=262144,K=256,N=64) + LN + GELU ----------------
// block: 128 rows x 64 cols, 256 threads, micro 8x4
__global__ __launch_bounds__(256) void conv1_kernel(
    const float* __restrict__ x, const float* __restrict__ cb,
    const float* __restrict__ lg, const float* __restrict__ lb) {
    __shared__ float As[16][128];
    __shared__ float Bs[16][64];
    __shared__ float rs[128][16];
    __shared__ float rq[128][16];
    const int tid = threadIdx.x;
    const int tx = tid & 15, ty = tid >> 4;
    const int m0 = blockIdx.x * 128;
    float acc[8][4];
#pragma unroll
    for (int r = 0; r < 8; r++)
#pragma unroll
        for (int c = 0; c < 4; c++) acc[r][c] = 0.f;

    for (int kc = 0; kc < 256; kc += 16) {
#pragma unroll
        for (int q = 0; q < 2; q++) {
            int gI = tid * 2 + q;
            int ml = gI >> 2;
            int k4 = (gI & 3) * 4;
            int m = m0 + ml;
            int bt = m >> 8, ij = m & 255, i = ij >> 4, j = ij & 15;
            int k = kc + k4;
            int kh = k >> 6, ko = k & 63;
            float4 v = *(const float4*)&x[bt * 65536 + (4 * i + kh) * 1024 + j * 64 + ko];
            As[k4 + 0][ml] = v.x; As[k4 + 1][ml] = v.y;
            As[k4 + 2][ml] = v.z; As[k4 + 3][ml] = v.w;
        }
        {
            int kl = tid >> 4, n4 = (tid & 15) * 4;
            *(float4*)&Bs[kl][n4] = *(const float4*)&g_w1r[(kc + kl) * 64 + n4];
        }
        __syncthreads();
#pragma unroll
        for (int k = 0; k < 16; k++) {
            float4 a0 = *(const float4*)&As[k][ty * 8];
            float4 a1 = *(const float4*)&As[k][ty * 8 + 4];
            float4 bv = *(const float4*)&Bs[k][tx * 4];
            float a[8] = {a0.x, a0.y, a0.z, a0.w, a1.x, a1.y, a1.z, a1.w};
            float bb[4] = {bv.x, bv.y, bv.z, bv.w};
#pragma unroll
            for (int r = 0; r < 8; r++)
#pragma unroll
                for (int c = 0; c < 4; c++) acc[r][c] = fmaf(a[r], bb[c], acc[r][c]);
        }
        __syncthreads();
    }
    // bias + LN partials
#pragma unroll
    for (int r = 0; r < 8; r++) {
        float s = 0.f, s2 = 0.f;
#pragma unroll
        for (int c = 0; c < 4; c++) {
            acc[r][c] += cb[tx * 4 + c];
            s += acc[r][c];
            s2 += acc[r][c] * acc[r][c];
        }
        rs[ty * 8 + r][tx] = s;
        rq[ty * 8 + r][tx] = s2;
    }
    __syncthreads();
#pragma unroll
    for (int r = 0; r < 8; r++) {
        int row = ty * 8 + r;
        float s = 0.f, s2 = 0.f;
#pragma unroll
        for (int t = 0; t < 16; t++) { s += rs[row][t]; s2 += rq[row][t]; }
        float mean = s * (1.f / 64.f);
        float var = s2 * (1.f / 64.f) - mean * mean;
        float inv = rsqrtf(var + 1e-5f);
        int m = m0 + row;
        float4 o;
        float* po = &o.x;
#pragma unroll
        for (int c = 0; c < 4; c++) {
            int col = tx * 4 + c;
            float y = (acc[r][c] - mean) * inv * lg[col] + lb[col];
            po[c] = gelu_exact(y);
        }
        *(float4*)&g_h1[m * 64 + tx * 4] = o;
    }
}

// ---------------- conv2 (patchify GEMM M=16384,K=1024,N=256) + LN + GELU ----------------
// block: 64 rows x 256 cols, 256 threads, micro 8x8
__global__ __launch_bounds__(256) void conv2_kernel(
    const float* __restrict__ cb, const float* __restrict__ lg, const float* __restrict__ lb) {
    __shared__ float As[16][64];
    __shared__ float Bs[16][256];
    __shared__ float rs[64][32];
    __shared__ float rq[64][32];
    const int tid = threadIdx.x;
    const int tx = tid & 31, ty = tid >> 5;
    const int m0 = blockIdx.x * 64;
    float acc[8][8];
#pragma unroll
    for (int r = 0; r < 8; r++)
#pragma unroll
        for (int c = 0; c < 8; c++) acc[r][c] = 0.f;

    for (int kc = 0; kc < 1024; kc += 16) {
        {
            int ml = tid >> 2, k4 = (tid & 3) * 4;
            int m = m0 + ml;
            int bt = m >> 4, ij = m & 15, oi = ij >> 2, oj = ij & 3;
            int k = kc + k4;
            int kh = k >> 8, ko = k & 255;
            float4 v = *(const float4*)&g_h1[bt * 16384 + (4 * oi + kh) * 1024 + oj * 256 + ko];
            As[k4 + 0][ml] = v.x; As[k4 + 1][ml] = v.y;
            As[k4 + 2][ml] = v.z; As[k4 + 3][ml] = v.w;
        }
#pragma unroll
        for (int q = 0; q < 4; q++) {
            int vI = tid + q * 256;
            int kl = vI >> 6, n4 = (vI & 63) * 4;
            *(float4*)&Bs[kl][n4] = *(const float4*)&g_w2r[(kc + kl) * 256 + n4];
        }
        __syncthreads();
#pragma unroll
        for (int k = 0; k < 16; k++) {
            float4 a0 = *(const float4*)&As[k][ty * 8];
            float4 a1 = *(const float4*)&As[k][ty * 8 + 4];
            float4 b0 = *(const float4*)&Bs[k][tx * 8];
            float4 b1 = *(const float4*)&Bs[k][tx * 8 + 4];
            float a[8] = {a0.x, a0.y, a0.z, a0.w, a1.x, a1.y, a1.z, a1.w};
            float bb[8] = {b0.x, b0.y, b0.z, b0.w, b1.x, b1.y, b1.z, b1.w};
#pragma unroll
            for (int r = 0; r < 8; r++)
#pragma unroll
                for (int c = 0; c < 8; c++) acc[r][c] = fmaf(a[r], bb[c], acc[r][c]);
        }
        __syncthreads();
    }
#pragma unroll
    for (int r = 0; r < 8; r++) {
        float s = 0.f, s2 = 0.f;
#pragma unroll
        for (int c = 0; c < 8; c++) {
            acc[r][c] += cb[tx * 8 + c];
            s += acc[r][c];
            s2 += acc[r][c] * acc[r][c];
        }
        rs[ty * 8 + r][tx] = s;
        rq[ty * 8 + r][tx] = s2;
    }
    __syncthreads();
#pragma unroll
    for (int r = 0; r < 8; r++) {
        int row = ty * 8 + r;
        float s = 0.f, s2 = 0.f;
#pragma unroll
        for (int t = 0; t < 32; t++) { s += rs[row][t]; s2 += rq[row][t]; }
        float mean = s * (1.f / 256.f);
        float var = s2 * (1.f / 256.f) - mean * mean;
        float inv = rsqrtf(var + 1e-5f);
        int m = m0 + row;
        float4 o0, o1;
        float* p0 = &o0.x; float* p1 = &o1.x;
#pragma unroll
        for (int c = 0; c < 4; c++) {
            int col = tx * 8 + c;
            float y = (acc[r][c] - mean) * inv * lg[col] + lb[col];
            p0[c] = gelu_exact(y);
        }
#pragma unroll
        for (int c = 4; c < 8; c++) {
            int col = tx * 8 + c;
            float y = (acc[r][c] - mean) * inv * lg[col] + lb[col];
            p1[c - 4] = gelu_exact(y);
        }
        *(float4*)&g_h2[m * 256 + tx * 8] = o0;
        *(float4*)&g_h2[m * 256 + tx * 8 + 4] = o1;
    }
}

// ---------------- fc GEMM (M=1024,K=4096,N=512) + bias ----------------
// block 64x64, 256 threads, micro 4x4; grid (N/64, M/64)
__global__ __launch_bounds__(256) void fc_kernel(
    const float* __restrict__ fw, const float* __restrict__ fb) {
    __shared__ float As[16][64];
    __shared__ float Bs[16][64];
    const int tid = threadIdx.x;
    const int tx = tid & 15, ty = tid >> 4;
    const int m0 = blockIdx.y * 64, n0 = blockIdx.x * 64;
    float acc[4][4];
#pragma unroll
    for (int r = 0; r < 4; r++)
#pragma unroll
        for (int c = 0; c < 4; c++) acc[r][c] = 0.f;

    for (int kc = 0; kc < 4096; kc += 16) {
        {
            int ml = tid >> 2, k4 = (tid & 3) * 4;
            float4 v = *(const float4*)&g_h2[(m0 + ml) * 4096 + kc + k4];
            As[k4 + 0][ml] = v.x; As[k4 + 1][ml] = v.y;
            As[k4 + 2][ml] = v.z; As[k4 + 3][ml] = v.w;
        }
        {
            int kl = tid >> 4, n4 = (tid & 15) * 4;
            *(float4*)&Bs[kl][n4] = *(const float4*)&fw[(kc + kl) * 512 + n0 + n4];
        }
        __syncthreads();
#pragma unroll
        for (int k = 0; k < 16; k++) {
            float4 av = *(const float4*)&As[k][ty * 4];
            float4 bv = *(const float4*)&Bs[k][tx * 4];
            float a[4] = {av.x, av.y, av.z, av.w};
            float bb[4] = {bv.x, bv.y, bv.z, bv.w};
#pragma unroll
            for (int r = 0; r < 4; r++)
#pragma unroll
                for (int c = 0; c < 4; c++) acc[r][c] = fmaf(a[r], bb[c], acc[r][c]);
        }
        __syncthreads();
    }
#pragma unroll
    for (int r = 0; r < 4; r++) {
        float4 o;
        float* po = &o.x;
#pragma unroll
        for (int c = 0; c < 4; c++) po[c] = acc[r][c] + fb[n0 + tx * 4 + c];
        *(float4*)&g_emb[(m0 + ty * 4 + r) * 512 + n0 + tx * 4] = o;
    }
}

// ---------------- Fourier gating: one block per batch row ----------------
__global__ __launch_bounds__(128) void gate_kernel(const float* __restrict__ w_gate) {
    const int b = blockIdx.x;
    const int tid = threadIdx.x;
    __shared__ float cs[8][16], sn[8][16];
    __shared__ float lgs[6];
    {
        int f = tid >> 4, t = tid & 15;
        float ang = -6.28318530717958647692f * (float)(f + 1) * (float)t * (1.f / 16.f);
        cs[f][t] = cosf(ang);
        sn[f][t] = sinf(ang);
    }
    if (tid < 6) lgs[tid] = 0.f;
    __syncthreads();
    float part[6] = {0.f, 0.f, 0.f, 0.f, 0.f, 0.f};
    for (int d = tid; d < 512; d += 128) {
        float v[16];
#pragma unroll
        for (int t = 0; t < 16; t++) v[t] = g_emb[(b * 16 + t) * 512 + d];
#pragma unroll
        for (int f = 0; f < 8; f++) {
            float re = 0.f, im = 0.f;
#pragma unroll
            for (int t = 0; t < 16; t++) {
                re = fmaf(v[t], cs[f][t], re);
                im = fmaf(v[t], sn[f][t], im);
            }
            float amp = sqrtf(re * re + im * im) * 0.25f;  // ortho norm 1/sqrt(16)
#pragma unroll
            for (int e = 0; e < 6; e++) part[e] = fmaf(amp, w_gate[f * 6 + e], part[e]);
        }
    }
#pragma unroll
    for (int e = 0; e < 6; e++) atomicAdd(&lgs[e], part[e]);
    __syncthreads();
    if (tid == 0) {
        float w[6];
#pragma unroll
        for (int e = 0; e < 6; e++) w[e] = lgs[e] * (1.f / 512.f);
        int i1 = 0;
        for (int e = 1; e < 6; e++) if (w[e] > w[i1]) i1 = e;
        int i2 = -1;
        for (int e = 0; e < 6; e++) {
            if (e == i1) continue;
            if (i2 < 0 || w[e] > w[i2]) i2 = e;
        }
        float e2 = expf(w[i2] - w[i1]);
        float s = 1.f + e2;
#pragma unroll
        for (int e = 0; e < 6; e++) g_gates[b * 6 + e] = 0.f;
        g_gates[b * 6 + i1] = 1.f / s;
        g_gates[b * 6 + i2] = e2 / s;
    }
}

// ---------------- experts (routed top-2) + exp/sum/log combine ----------------
// grid (4 ftiles, 64 b); block 256 threads: 16 rows(t) x 16 colgroups(8 cols)
__global__ __launch_bounds__(256) void expert_kernel(
    const float* __restrict__ ew, const float* __restrict__ eb, float* __restrict__ out) {
    __shared__ float As[32][16];
    __shared__ float Bs[32][128];
    const int tid = threadIdx.x;
    const int tx = tid & 15, ty = tid >> 4;
    const int b = blockIdx.y;
    const int fx = blockIdx.x * 128;
    float comb[8];
#pragma unroll
    for (int c = 0; c < 8; c++) comb[c] = 0.f;

    for (int e = 0; e < 6; e++) {
        float gv = g_gates[b * 6 + e];
        if (gv == 0.f) continue;   // uniform per block
        float acc[8];
#pragma unroll
        for (int c = 0; c < 8; c++) acc[c] = 0.f;
        for (int kc = 0; kc < 512; kc += 32) {
            if (tid < 128) {
                int ml = tid >> 3, k4 = (tid & 7) * 4;
                float4 v = *(const float4*)&g_emb[(b * 16 + ml) * 512 + kc + k4];
                As[k4 + 0][ml] = v.x; As[k4 + 1][ml] = v.y;
                As[k4 + 2][ml] = v.z; As[k4 + 3][ml] = v.w;
            }
#pragma unroll
            for (int q = 0; q < 4; q++) {
                int vI = tid + q * 256;
                int kl = vI >> 5, n4 = (vI & 31) * 4;
                *(float4*)&Bs[kl][n4] = *(const float4*)&ew[(e * 512 + kc + kl) * 512 + fx + n4];
            }
            __syncthreads();
#pragma unroll
            for (int k = 0; k < 32; k++) {
                float a = As[k][ty];
                float4 b0 = *(const float4*)&Bs[k][tx * 8];
                float4 b1 = *(const float4*)&Bs[k][tx * 8 + 4];
                acc[0] = fmaf(a, b0.x, acc[0]);
                acc[1] = fmaf(a, b0.y, acc[1]);
                acc[2] = fmaf(a, b0.z, acc[2]);
                acc[3] = fmaf(a, b0.w, acc[3]);
                acc[4] = fmaf(a, b1.x, acc[4]);
                acc[5] = fmaf(a, b1.y, acc[5]);
                acc[6] = fmaf(a, b1.z, acc[6]);
                acc[7] = fmaf(a, b1.w, acc[7]);
            }
            __syncthreads();
        }
#pragma unroll
        for (int c = 0; c < 8; c++) {
            float z = acc[c] + eb[e * 512 + fx + tx * 8 + c];
            comb[c] = fmaf(gv, expf(z), comb[c]);
        }
    }
#pragma unroll
    for (int c = 0; c < 8; c++) {
        float v = comb[c];
        if (v == 0.f) v = 2.220446049250313e-16f;
        out[(b * 16 + ty) * 512 + fx + tx * 8 + c] = logf(v);
    }
}

// ---------------- launch ----------------
extern "C" void kernel_launch(void* const* d_in, const int* in_sizes, int n_in,
                              void* d_out, int out_size) {
    const float* x       = (const float*)d_in[0];
    const float* conv1_w = (const float*)d_in[1];
    const float* conv1_b = (const float*)d_in[2];
    const float* ln1_g   = (const float*)d_in[3];
    const float* ln1_b   = (const float*)d_in[4];
    const float* conv2_w = (const float*)d_in[5];
    const float* conv2_b = (const float*)d_in[6];
    const float* ln2_g   = (const float*)d_in[7];
    const float* ln2_b   = (const float*)d_in[8];
    const float* fc_w    = (const float*)d_in[9];
    const float* fc_b    = (const float*)d_in[10];
    const float* w_gate  = (const float*)d_in[11];
    const float* exp_w   = (const float*)d_in[12];
    const float* exp_b   = (const float*)d_in[13];
    float* out = (float*)d_out;

    prep_kernel<<<1024, 256>>>(conv1_w, conv2_w);
    conv1_kernel<<<2048, 256>>>(x, conv1_b, ln1_g, ln1_b);
    conv2_kernel<<<256, 256>>>(conv2_b, ln2_g, ln2_b);
    fc_kernel<<<dim3(8, 16), 256>>>(fc_w, fc_b);
    gate_kernel<<<64, 128>>>(w_gate);
    expert_kernel<<<dim3(4, 64), 256>>>(exp_w, exp_b, out);
}

// round 9
// speedup vs baseline: 1.1516x; 1.0966x over previous
#include <cuda_runtime.h>
#include <cuda_bf16.h>
#include <cstdint>
#include <math.h>

// ---------------- scratch (static device globals; no allocation) ----------------
__device__ __align__(16) float g_h1[16777216];   // (1024, 16, 16, 64)
__device__ __align__(16) float g_h2[4194304];    // (1024, 4096)
__device__ __align__(16) float g_emb[524288];    // (1024, 512)
__device__ __align__(16) float g_w1r[16384];     // conv1 w rearranged (k=256, cout=64)
__device__ __align__(16) float g_w2r[262144];    // conv2 w rearranged (k=1024, cout=256)
__device__ __align__(16) float g_gates[384];     // (64, 6)
__device__ __align__(16) __nv_bfloat16 g_fwb_hi[2097152];  // fc_w^T hi [512][4096]
__device__ __align__(16) __nv_bfloat16 g_fwb_lo[2097152];  // fc_w^T lo

// ---------------- weight rearrangement (verbatim from passing R3) ----------------
__global__ void prep_kernel(const float* __restrict__ w1, const float* __restrict__ w2) {
    int idx = blockIdx.x * 256 + threadIdx.x;
    if (idx < 16384) {
        int k = idx >> 6, c = idx & 63;
        int kh = k >> 6, kw = (k >> 4) & 3, ci = k & 15;
        g_w1r[idx] = w1[c * 256 + ci * 16 + kh * 4 + kw];
    }
    if (idx < 262144) {
        int k = idx >> 8, co = idx & 255;
        int kh = k >> 8, kw = (k >> 6) & 3, ci = k & 63;
        g_w2r[idx] = w2[co * 1024 + ci * 16 + kh * 4 + kw];
    }
}

// fc_w fp32 [4096][512] -> bf16 hi/lo [512][4096]
__global__ __launch_bounds__(256) void transpose_cvt(const float* __restrict__ src) {
    __shared__ float tile[32][33];
    int c0 = blockIdx.x * 32, r0 = blockIdx.y * 32;
#pragma unroll
    for (int q = 0; q < 4; q++)
        tile[threadIdx.y + q * 8][threadIdx.x] =
            src[(size_t)(r0 + threadIdx.y + q * 8) * 512 + c0 + threadIdx.x];
    __syncthreads();
#pragma unroll
    for (int q = 0; q < 4; q++) {
        int c = c0 + threadIdx.y + q * 8;
        float v = tile[threadIdx.x][threadIdx.y + q * 8];
        __nv_bfloat16 h = __float2bfloat16(v);
        g_fwb_hi[(size_t)c * 4096 + r0 + threadIdx.x] = h;
        g_fwb_lo[(size_t)c * 4096 + r0 + threadIdx.x] =
            __float2bfloat16(v - __bfloat162float(h));
    }
}

__device__ __forceinline__ float gelu_exact(float y) {
    return 0.5f * y * (1.f + erff(y * 0.70710678118654752440f));
}

// ---------------- conv1 (verbatim from passing R3) ----------------
__global__ __launch_bounds__(256) void conv1_kernel(
    const float* __restrict__ x, const float* __restrict__ cb,
    const float* __restrict__ lg, const float* __restrict__ lb) {
    __shared__ float As[16][128];
    __shared__ float Bs[16][64];
    __shared__ float rs[128][16];
    __shared__ float rq[128][16];
    const int tid = threadIdx.x;
    const int tx = tid & 15, ty = tid >> 4;
    const int m0 = blockIdx.x * 128;
    float acc[8][4];
#pragma unroll
    for (int r = 0; r < 8; r++)
#pragma unroll
        for (int c = 0; c < 4; c++) acc[r][c] = 0.f;

    for (int kc = 0; kc < 256; kc += 16) {
#pragma unroll
        for (int q = 0; q < 2; q++) {
            int gI = tid * 2 + q;
            int ml = gI >> 2;
            int k4 = (gI & 3) * 4;
            int m = m0 + ml;
            int bt = m >> 8, ij = m & 255, i = ij >> 4, j = ij & 15;
            int k = kc + k4;
            int kh = k >> 6, ko = k & 63;
            float4 v = *(const float4*)&x[bt * 65536 + (4 * i + kh) * 1024 + j * 64 + ko];
            As[k4 + 0][ml] = v.x; As[k4 + 1][ml] = v.y;
            As[k4 + 2][ml] = v.z; As[k4 + 3][ml] = v.w;
        }
        {
            int kl = tid >> 4, n4 = (tid & 15) * 4;
            *(float4*)&Bs[kl][n4] = *(const float4*)&g_w1r[(kc + kl) * 64 + n4];
        }
        __syncthreads();
#pragma unroll
        for (int k = 0; k < 16; k++) {
            float4 a0 = *(const float4*)&As[k][ty * 8];
            float4 a1 = *(const float4*)&As[k][ty * 8 + 4];
            float4 bv = *(const float4*)&Bs[k][tx * 4];
            float a[8] = {a0.x, a0.y, a0.z, a0.w, a1.x, a1.y, a1.z, a1.w};
            float bb[4] = {bv.x, bv.y, bv.z, bv.w};
#pragma unroll
            for (int r = 0; r < 8; r++)
#pragma unroll
                for (int c = 0; c < 4; c++) acc[r][c] = fmaf(a[r], bb[c], acc[r][c]);
        }
        __syncthreads();
    }
#pragma unroll
    for (int r = 0; r < 8; r++) {
        float s = 0.f, s2 = 0.f;
#pragma unroll
        for (int c = 0; c < 4; c++) {
            acc[r][c] += cb[tx * 4 + c];
            s += acc[r][c];
            s2 += acc[r][c] * acc[r][c];
        }
        rs[ty * 8 + r][tx] = s;
        rq[ty * 8 + r][tx] = s2;
    }
    __syncthreads();
#pragma unroll
    for (int r = 0; r < 8; r++) {
        int row = ty * 8 + r;
        float s = 0.f, s2 = 0.f;
#pragma unroll
        for (int t = 0; t < 16; t++) { s += rs[row][t]; s2 += rq[row][t]; }
        float mean = s * (1.f / 64.f);
        float var = s2 * (1.f / 64.f) - mean * mean;
        float inv = rsqrtf(var + 1e-5f);
        int m = m0 + row;
        float4 o;
        float* po = &o.x;
#pragma unroll
        for (int c = 0; c < 4; c++) {
            int col = tx * 4 + c;
            float y = (acc[r][c] - mean) * inv * lg[col] + lb[col];
            po[c] = gelu_exact(y);
        }
        *(float4*)&g_h1[m * 64 + tx * 4] = o;
    }
}

// ---------------- conv2 (verbatim from passing R3) ----------------
__global__ __launch_bounds__(256) void conv2_kernel(
    const float* __restrict__ cb, const float* __restrict__ lg, const float* __restrict__ lb) {
    __shared__ float As[16][64];
    __shared__ float Bs[16][256];
    __shared__ float rs[64][32];
    __shared__ float rq[64][32];
    const int tid = threadIdx.x;
    const int tx = tid & 31, ty = tid >> 5;
    const int m0 = blockIdx.x * 64;
    float acc[8][8];
#pragma unroll
    for (int r = 0; r < 8; r++)
#pragma unroll
        for (int c = 0; c < 8; c++) acc[r][c] = 0.f;

    for (int kc = 0; kc < 1024; kc += 16) {
        {
            int ml = tid >> 2, k4 = (tid & 3) * 4;
            int m = m0 + ml;
            int bt = m >> 4, ij = m & 15, oi = ij >> 2, oj = ij & 3;
            int k = kc + k4;
            int kh = k >> 8, ko = k & 255;
            float4 v = *(const float4*)&g_h1[bt * 16384 + (4 * oi + kh) * 1024 + oj * 256 + ko];
            As[k4 + 0][ml] = v.x; As[k4 + 1][ml] = v.y;
            As[k4 + 2][ml] = v.z; As[k4 + 3][ml] = v.w;
        }
#pragma unroll
        for (int q = 0; q < 4; q++) {
            int vI = tid + q * 256;
            int kl = vI >> 6, n4 = (vI & 63) * 4;
            *(float4*)&Bs[kl][n4] = *(const float4*)&g_w2r[(kc + kl) * 256 + n4];
        }
        __syncthreads();
#pragma unroll
        for (int k = 0; k < 16; k++) {
            float4 a0 = *(const float4*)&As[k][ty * 8];
            float4 a1 = *(const float4*)&As[k][ty * 8 + 4];
            float4 b0 = *(const float4*)&Bs[k][tx * 8];
            float4 b1 = *(const float4*)&Bs[k][tx * 8 + 4];
            float a[8] = {a0.x, a0.y, a0.z, a0.w, a1.x, a1.y, a1.z, a1.w};
            float bb[8] = {b0.x, b0.y, b0.z, b0.w, b1.x, b1.y, b1.z, b1.w};
#pragma unroll
            for (int r = 0; r < 8; r++)
#pragma unroll
                for (int c = 0; c < 8; c++) acc[r][c] = fmaf(a[r], bb[c], acc[r][c]);
        }
        __syncthreads();
    }
#pragma unroll
    for (int r = 0; r < 8; r++) {
        float s = 0.f, s2 = 0.f;
#pragma unroll
        for (int c = 0; c < 8; c++) {
            acc[r][c] += cb[tx * 8 + c];
            s += acc[r][c];
            s2 += acc[r][c] * acc[r][c];
        }
        rs[ty * 8 + r][tx] = s;
        rq[ty * 8 + r][tx] = s2;
    }
    __syncthreads();
#pragma unroll
    for (int r = 0; r < 8; r++) {
        int row = ty * 8 + r;
        float s = 0.f, s2 = 0.f;
#pragma unroll
        for (int t = 0; t < 32; t++) { s += rs[row][t]; s2 += rq[row][t]; }
        float mean = s * (1.f / 256.f);
        float var = s2 * (1.f / 256.f) - mean * mean;
        float inv = rsqrtf(var + 1e-5f);
        int m = m0 + row;
        float4 o0, o1;
        float* p0 = &o0.x; float* p1 = &o1.x;
#pragma unroll
        for (int c = 0; c < 4; c++) {
            int col = tx * 8 + c;
            float y = (acc[r][c] - mean) * inv * lg[col] + lb[col];
            p0[c] = gelu_exact(y);
        }
#pragma unroll
        for (int c = 4; c < 8; c++) {
            int col = tx * 8 + c;
            float y = (acc[r][c] - mean) * inv * lg[col] + lb[col];
            p1[c - 4] = gelu_exact(y);
        }
        *(float4*)&g_h2[m * 256 + tx * 8] = o0;
        *(float4*)&g_h2[m * 256 + tx * 8 + 4] = o1;
    }
}

// ---------------- fc via mma.sync bf16 hi/lo (THE ONE NEW KERNEL) ----------------
__device__ __forceinline__ uint32_t smem_u32(const void* p) {
    uint32_t a;
    asm("{ .reg .u64 t; cvta.to.shared.u64 t, %1; cvt.u32.u64 %0, t; }" : "=r"(a) : "l"(p));
    return a;
}
__device__ __forceinline__ void ldsm4(uint32_t r[4], uint32_t a) {
    asm volatile("ldmatrix.sync.aligned.m8n8.x4.shared.b16 {%0,%1,%2,%3}, [%4];"
                 : "=r"(r[0]), "=r"(r[1]), "=r"(r[2]), "=r"(r[3]) : "r"(a));
}
__device__ __forceinline__ void mma16816(float c[4], const uint32_t a[4], const uint32_t b[2]) {
    asm volatile(
        "mma.sync.aligned.m16n8k16.row.col.f32.bf16.bf16.f32 "
        "{%0,%1,%2,%3}, {%4,%5,%6,%7}, {%8,%9}, {%0,%1,%2,%3};"
        : "+f"(c[0]), "+f"(c[1]), "+f"(c[2]), "+f"(c[3])
        : "r"(a[0]), "r"(a[1]), "r"(a[2]), "r"(a[3]), "r"(b[0]), "r"(b[1]));
}
struct __align__(8) BF4 { __nv_bfloat16 h[4]; };

// BM=64, BN=128, BK=32; 256 threads = 8 warps as 4(m) x 2(n); warp tile 16x64.
// smem: A_HI 0 (5120), A_LO 5120, B_HI 10240 (10240), B_LO 20480; total 30720.
__global__ __launch_bounds__(256, 1) void fc_mma(const float* __restrict__ fb) {
    __shared__ __align__(16) char smem[30720];
    const uint32_t sb = smem_u32(smem);
    const int tid = threadIdx.x, lane = tid & 31, w = tid >> 5;
    const int n0 = blockIdx.x * 128, m0 = blockIdx.y * 64;
    const int mrow0 = (w >> 1) * 16, ncol0 = (w & 1) * 64;
    constexpr int A_HI = 0, A_LO = 5120, B_HI = 10240, B_LO = 20480;

    float acc[8][4];
#pragma unroll
    for (int b = 0; b < 8; b++)
#pragma unroll
        for (int c = 0; c < 4; c++) acc[b][c] = 0.f;

    for (int kc = 0; kc < 4096; kc += 32) {
        __syncthreads();
        // A: 64 rows x 32 fp32 -> split bf16 hi/lo. 512 float4; 2 per thread.
#pragma unroll
        for (int q = 0; q < 2; q++) {
            int idx = tid * 2 + q;
            int ml = idx >> 3, kp = idx & 7;
            float4 v = *(const float4*)&g_h2[(size_t)(m0 + ml) * 4096 + kc + kp * 4];
            float f[4] = {v.x, v.y, v.z, v.w};
            BF4 hi, lo;
#pragma unroll
            for (int t = 0; t < 4; t++) {
                hi.h[t] = __float2bfloat16(f[t]);
                lo.h[t] = __float2bfloat16(f[t] - __bfloat162float(hi.h[t]));
            }
            *(uint2*)(smem + A_HI + ml * 80 + kp * 8) = *(uint2*)&hi;
            *(uint2*)(smem + A_LO + ml * 80 + kp * 8) = *(uint2*)&lo;
        }
        // B: 128 rows x 32 bf16 (hi + lo). 512 uint4 each; 2 per thread.
#pragma unroll
        for (int it = 0; it < 2; it++) {
            int idx = tid + it * 256;
            int r = idx >> 2, kp = idx & 3;
            size_t src = (size_t)(n0 + r) * 4096 + kc + kp * 8;
            *(uint4*)(smem + B_HI + r * 80 + kp * 16) = *(const uint4*)&g_fwb_hi[src];
            *(uint4*)(smem + B_LO + r * 80 + kp * 16) = *(const uint4*)&g_fwb_lo[src];
        }
        __syncthreads();
        // warp MMA: 2 k-steps of 16
#pragma unroll
        for (int ks = 0; ks < 2; ks++) {
            const int k0 = ks * 16;
            uint32_t ah[4], al[4];
            {
                uint32_t ro = (uint32_t)((mrow0 + (lane & 15)) * 80 + (k0 + (lane >> 4) * 8) * 2);
                ldsm4(ah, sb + A_HI + ro);
                ldsm4(al, sb + A_LO + ro);
            }
            uint32_t bh[8][2], bl[8][2];
#pragma unroll
            for (int np = 0; np < 4; np++) {
                uint32_t ro = (uint32_t)((ncol0 + np * 16 + (lane & 7) + ((lane >> 4) * 8)) * 80 +
                                         (k0 + ((lane >> 3) & 1) * 8) * 2);
                uint32_t t[4];
                ldsm4(t, sb + B_HI + ro);
                bh[np * 2][0] = t[0]; bh[np * 2][1] = t[1];
                bh[np * 2 + 1][0] = t[2]; bh[np * 2 + 1][1] = t[3];
                ldsm4(t, sb + B_LO + ro);
                bl[np * 2][0] = t[0]; bl[np * 2][1] = t[1];
                bl[np * 2 + 1][0] = t[2]; bl[np * 2 + 1][1] = t[3];
            }
#pragma unroll
            for (int nf = 0; nf < 8; nf++) {
                mma16816(acc[nf], ah, bh[nf]);
                mma16816(acc[nf], ah, bl[nf]);
                mma16816(acc[nf], al, bh[nf]);
            }
        }
    }
    // epilogue: + bias -> g_emb
    int g = lane >> 2, t2 = (lane & 3) * 2;
    int row = m0 + mrow0 + g;
#pragma unroll
    for (int nf = 0; nf < 8; nf++) {
        int col = n0 + ncol0 + nf * 8 + t2;
        float2 b01 = *(const float2*)&fb[col];
        *(float2*)&g_emb[(size_t)row * 512 + col] =
            make_float2(acc[nf][0] + b01.x, acc[nf][1] + b01.y);
        *(float2*)&g_emb[(size_t)(row + 8) * 512 + col] =
            make_float2(acc[nf][2] + b01.x, acc[nf][3] + b01.y);
    }
}

// ---------------- Fourier gating (verbatim from passing R3) ----------------
__global__ __launch_bounds__(128) void gate_kernel(const float* __restrict__ w_gate) {
    const int b = blockIdx.x;
    const int tid = threadIdx.x;
    __shared__ float cs[8][16], sn[8][16];
    __shared__ float lgs[6];
    {
        int f = tid >> 4, t = tid & 15;
        float ang = -6.28318530717958647692f * (float)(f + 1) * (float)t * (1.f / 16.f);
        cs[f][t] = cosf(ang);
        sn[f][t] = sinf(ang);
    }
    if (tid < 6) lgs[tid] = 0.f;
    __syncthreads();
    float part[6] = {0.f, 0.f, 0.f, 0.f, 0.f, 0.f};
    for (int d = tid; d < 512; d += 128) {
        float v[16];
#pragma unroll
        for (int t = 0; t < 16; t++) v[t] = g_emb[(b * 16 + t) * 512 + d];
#pragma unroll
        for (int f = 0; f < 8; f++) {
            float re = 0.f, im = 0.f;
#pragma unroll
            for (int t = 0; t < 16; t++) {
                re = fmaf(v[t], cs[f][t], re);
                im = fmaf(v[t], sn[f][t], im);
            }
            float amp = sqrtf(re * re + im * im) * 0.25f;
#pragma unroll
            for (int e = 0; e < 6; e++) part[e] = fmaf(amp, w_gate[f * 6 + e], part[e]);
        }
    }
#pragma unroll
    for (int e = 0; e < 6; e++) atomicAdd(&lgs[e], part[e]);
    __syncthreads();
    if (tid == 0) {
        float wv[6];
#pragma unroll
        for (int e = 0; e < 6; e++) wv[e] = lgs[e] * (1.f / 512.f);
        int i1 = 0;
        for (int e = 1; e < 6; e++) if (wv[e] > wv[i1]) i1 = e;
        int i2 = -1;
        for (int e = 0; e < 6; e++) {
            if (e == i1) continue;
            if (i2 < 0 || wv[e] > wv[i2]) i2 = e;
        }
        float e2 = expf(wv[i2] - wv[i1]);
        float s = 1.f + e2;
#pragma unroll
        for (int e = 0; e < 6; e++) g_gates[b * 6 + e] = 0.f;
        g_gates[b * 6 + i1] = 1.f / s;
        g_gates[b * 6 + i2] = e2 / s;
    }
}

// ---------------- experts (verbatim from passing R3) ----------------
__global__ __launch_bounds__(256) void expert_kernel(
    const float* __restrict__ ew, const float* __restrict__ eb, float* __restrict__ out) {
    __shared__ float As[32][16];
    __shared__ float Bs[32][128];
    const int tid = threadIdx.x;
    const int tx = tid & 15, ty = tid >> 4;
    const int b = blockIdx.y;
    const int fx = blockIdx.x * 128;
    float comb[8];
#pragma unroll
    for (int c = 0; c < 8; c++) comb[c] = 0.f;

    for (int e = 0; e < 6; e++) {
        float gv = g_gates[b * 6 + e];
        if (gv == 0.f) continue;
        float acc[8];
#pragma unroll
        for (int c = 0; c < 8; c++) acc[c] = 0.f;
        for (int kc = 0; kc < 512; kc += 32) {
            if (tid < 128) {
                int ml = tid >> 3, k4 = (tid & 7) * 4;
                float4 v = *(const float4*)&g_emb[(b * 16 + ml) * 512 + kc + k4];
                As[k4 + 0][ml] = v.x; As[k4 + 1][ml] = v.y;
                As[k4 + 2][ml] = v.z; As[k4 + 3][ml] = v.w;
            }
#pragma unroll
            for (int q = 0; q < 4; q++) {
                int vI = tid + q * 256;
                int kl = vI >> 5, n4 = (vI & 31) * 4;
                *(float4*)&Bs[kl][n4] = *(const float4*)&ew[(e * 512 + kc + kl) * 512 + fx + n4];
            }
            __syncthreads();
#pragma unroll
            for (int k = 0; k < 32; k++) {
                float a = As[k][ty];
                float4 b0 = *(const float4*)&Bs[k][tx * 8];
                float4 b1 = *(const float4*)&Bs[k][tx * 8 + 4];
                acc[0] = fmaf(a, b0.x, acc[0]);
                acc[1] = fmaf(a, b0.y, acc[1]);
                acc[2] = fmaf(a, b0.z, acc[2]);
                acc[3] = fmaf(a, b0.w, acc[3]);
                acc[4] = fmaf(a, b1.x, acc[4]);
                acc[5] = fmaf(a, b1.y, acc[5]);
                acc[6] = fmaf(a, b1.z, acc[6]);
                acc[7] = fmaf(a, b1.w, acc[7]);
            }
            __syncthreads();
        }
#pragma unroll
        for (int c = 0; c < 8; c++) {
            float z = acc[c] + eb[e * 512 + fx + tx * 8 + c];
            comb[c] = fmaf(gv, expf(z), comb[c]);
        }
    }
#pragma unroll
    for (int c = 0; c < 8; c++) {
        float v = comb[c];
        if (v == 0.f) v = 2.220446049250313e-16f;
        out[(b * 16 + ty) * 512 + fx + tx * 8 + c] = logf(v);
    }
}

// ---------------- launch ----------------
extern "C" void kernel_launch(void* const* d_in, const int* in_sizes, int n_in,
                              void* d_out, int out_size) {
    const float* x       = (const float*)d_in[0];
    const float* conv1_w = (const float*)d_in[1];
    const float* conv1_b = (const float*)d_in[2];
    const float* ln1_g   = (const float*)d_in[3];
    const float* ln1_b   = (const float*)d_in[4];
    const float* conv2_w = (const float*)d_in[5];
    const float* conv2_b = (const float*)d_in[6];
    const float* ln2_g   = (const float*)d_in[7];
    const float* ln2_b   = (const float*)d_in[8];
    const float* fc_w    = (const float*)d_in[9];
    const float* fc_b    = (const float*)d_in[10];
    const float* w_gate  = (const float*)d_in[11];
    const float* exp_w   = (const float*)d_in[12];
    const float* exp_b   = (const float*)d_in[13];
    float* out = (float*)d_out;

    prep_kernel<<<1024, 256>>>(conv1_w, conv2_w);
    transpose_cvt<<<dim3(16, 128), dim3(32, 8)>>>(fc_w);
    conv1_kernel<<<2048, 256>>>(x, conv1_b, ln1_g, ln1_b);
    conv2_kernel<<<256, 256>>>(conv2_b, ln2_g, ln2_b);
    fc_mma<<<dim3(4, 16), 256>>>(fc_b);
    gate_kernel<<<64, 128>>>(w_gate);
    expert_kernel<<<dim3(4, 64), 256>>>(exp_w, exp_b, out);
}

// round 10
// speedup vs baseline: 1.3013x; 1.1300x over previous
#include <cuda_runtime.h>
#include <cuda_bf16.h>
#include <cstdint>
#include <math.h>

// ============================ scratch ============================
__device__ __align__(16) float g_h1[16777216];   // (1024,16,16,64) conv1 out
__device__ __align__(16) float g_c2[4194304];    // conv2 raw GEMM out (16384,256)
__device__ __align__(16) float g_h2[4194304];    // (1024,4096) fc A
__device__ __align__(16) float g_emb[524288];    // (1024,512)
__device__ __align__(16) float g_gates[384];     // (64,6)
__device__ __align__(16) __nv_bfloat16 g_w1b_hi[16384],   g_w1b_lo[16384];    // [64][256]
__device__ __align__(16) __nv_bfloat16 g_w2b_hi[262144],  g_w2b_lo[262144];   // [256][1024]
__device__ __align__(16) __nv_bfloat16 g_fwb_hi[2097152], g_fwb_lo[2097152];  // [512][4096]

// ============================ MMA helpers (validated in R9) ============================
__device__ __forceinline__ uint32_t smem_u32(const void* p) {
    uint32_t a;
    asm("{ .reg .u64 t; cvta.to.shared.u64 t, %1; cvt.u32.u64 %0, t; }" : "=r"(a) : "l"(p));
    return a;
}
__device__ __forceinline__ void ldsm4(uint32_t r[4], uint32_t a) {
    asm volatile("ldmatrix.sync.aligned.m8n8.x4.shared.b16 {%0,%1,%2,%3}, [%4];"
                 : "=r"(r[0]), "=r"(r[1]), "=r"(r[2]), "=r"(r[3]) : "r"(a));
}
__device__ __forceinline__ void mma16816(float c[4], const uint32_t a[4], const uint32_t b[2]) {
    asm volatile(
        "mma.sync.aligned.m16n8k16.row.col.f32.bf16.bf16.f32 "
        "{%0,%1,%2,%3}, {%4,%5,%6,%7}, {%8,%9}, {%0,%1,%2,%3};"
        : "+f"(c[0]), "+f"(c[1]), "+f"(c[2]), "+f"(c[3])
        : "r"(a[0]), "r"(a[1]), "r"(a[2]), "r"(a[3]), "r"(b[0]), "r"(b[1]));
}
struct __align__(8)  BF4 { __nv_bfloat16 h[4]; };

__device__ __forceinline__ float gelu_exact(float y) {
    return 0.5f * y * (1.f + erff(y * 0.70710678118654752440f));
}

// warp tile 16x64, one BK=32 chunk, hi/lo split (3 mma per frag pair). rows: 80B stride.
__device__ __forceinline__ void warp_mma16(
    uint32_t aHi, uint32_t aLo, uint32_t bHi, uint32_t bLo,
    int mrow0, int ncol0, int lane, float acc[8][4]) {
#pragma unroll
    for (int ks = 0; ks < 2; ks++) {
        const int k0 = ks * 16;
        uint32_t ah[4], al[4];
        {
            uint32_t ro = (uint32_t)((mrow0 + (lane & 15)) * 80 + (k0 + (lane >> 4) * 8) * 2);
            ldsm4(ah, aHi + ro);
            ldsm4(al, aLo + ro);
        }
        uint32_t bh[8][2], bl[8][2];
#pragma unroll
        for (int np = 0; np < 4; np++) {
            uint32_t ro = (uint32_t)((ncol0 + np * 16 + (lane & 7) + ((lane >> 4) * 8)) * 80 +
                                     (k0 + ((lane >> 3) & 1) * 8) * 2);
            uint32_t t[4];
            ldsm4(t, bHi + ro);
            bh[np * 2][0] = t[0]; bh[np * 2][1] = t[1];
            bh[np * 2 + 1][0] = t[2]; bh[np * 2 + 1][1] = t[3];
            ldsm4(t, bLo + ro);
            bl[np * 2][0] = t[0]; bl[np * 2][1] = t[1];
            bl[np * 2 + 1][0] = t[2]; bl[np * 2 + 1][1] = t[3];
        }
#pragma unroll
        for (int nf = 0; nf < 8; nf++) {
            mma16816(acc[nf], ah, bh[nf]);
            mma16816(acc[nf], ah, bl[nf]);
            mma16816(acc[nf], al, bh[nf]);
        }
    }
}

// ============================ weight prep ============================
// conv weights -> n-major k-contig bf16 hi/lo. conv1 k = kh*64+kw*16+ci; conv2 k = kh*256+kw*64+ci
__global__ __launch_bounds__(256) void prep_kernel(const float* __restrict__ w1,
                                                   const float* __restrict__ w2) {
    int idx = blockIdx.x * 256 + threadIdx.x;
    if (idx < 16384) {
        int n = idx >> 8, k = idx & 255;
        int kh = k >> 6, kw = (k >> 4) & 3, ci = k & 15;
        float v = w1[n * 256 + ci * 16 + kh * 4 + kw];
        __nv_bfloat16 h = __float2bfloat16(v);
        g_w1b_hi[idx] = h;
        g_w1b_lo[idx] = __float2bfloat16(v - __bfloat162float(h));
    }
    if (idx < 262144) {
        int n = idx >> 10, k = idx & 1023;
        int kh = k >> 8, kw = (k >> 6) & 3, ci = k & 63;
        float v = w2[n * 1024 + ci * 16 + kh * 4 + kw];
        __nv_bfloat16 h = __float2bfloat16(v);
        g_w2b_hi[idx] = h;
        g_w2b_lo[idx] = __float2bfloat16(v - __bfloat162float(h));
    }
}

// fc_w fp32 [4096][512] -> bf16 hi/lo [512][4096] (validated R9)
__global__ __launch_bounds__(256) void transpose_cvt(const float* __restrict__ src) {
    __shared__ float tile[32][33];
    int c0 = blockIdx.x * 32, r0 = blockIdx.y * 32;
#pragma unroll
    for (int q = 0; q < 4; q++)
        tile[threadIdx.y + q * 8][threadIdx.x] =
            src[(size_t)(r0 + threadIdx.y + q * 8) * 512 + c0 + threadIdx.x];
    __syncthreads();
#pragma unroll
    for (int q = 0; q < 4; q++) {
        int c = c0 + threadIdx.y + q * 8;
        float v = tile[threadIdx.x][threadIdx.y + q * 8];
        __nv_bfloat16 h = __float2bfloat16(v);
        g_fwb_hi[(size_t)c * 4096 + r0 + threadIdx.x] = h;
        g_fwb_lo[(size_t)c * 4096 + r0 + threadIdx.x] =
            __float2bfloat16(v - __bfloat162float(h));
    }
}

// ============================ conv1 via mma: M=262144 K=256 N=64 + LN + GELU ============================
// BM=128, BN=64, 8 warps over M (warp tile 16x64, ncol0=0).
// smem mainloop: A_HI 0 (10240), A_LO 10240, B_HI 20480 (5120), B_LO 25600 (end 30720)
// epilogue C overlay [128][65] f = 33280 bytes (static smem 33280).
__global__ __launch_bounds__(256, 1) void conv1_mma(
    const float* __restrict__ x, const float* __restrict__ cb,
    const float* __restrict__ lg, const float* __restrict__ lb) {
    __shared__ __align__(16) char smem[33280];
    const uint32_t sb = smem_u32(smem);
    const int tid = threadIdx.x, lane = tid & 31, w = tid >> 5;
    const int m0 = blockIdx.x * 128;
    constexpr int A_HI = 0, A_LO = 10240, B_HI = 20480, B_LO = 25600;
    const int mrow0 = w * 16;

    float acc[8][4];
#pragma unroll
    for (int b = 0; b < 8; b++)
#pragma unroll
        for (int c = 0; c < 4; c++) acc[b][c] = 0.f;

    for (int ch = 0; ch < 8; ch++) {
        const int kc = ch * 32;
        __syncthreads();
        // A: 128 rows x 32 fp32 = 1024 float4; 4 per thread; split to bf16 hi/lo
#pragma unroll
        for (int q = 0; q < 4; q++) {
            int idx = tid * 4 + q;
            int ml = idx >> 3, kp = idx & 7;
            int m = m0 + ml;
            int bt = m >> 8, ij = m & 255, i = ij >> 4, j = ij & 15;
            int k = kc + kp * 4;
            int kh = k >> 6, ko = k & 63;
            float4 v = *(const float4*)&x[(size_t)bt * 65536 + (4 * i + kh) * 1024 + j * 64 + ko];
            float f[4] = {v.x, v.y, v.z, v.w};
            BF4 hi, lo;
#pragma unroll
            for (int t = 0; t < 4; t++) {
                hi.h[t] = __float2bfloat16(f[t]);
                lo.h[t] = __float2bfloat16(f[t] - __bfloat162float(hi.h[t]));
            }
            *(uint2*)(smem + A_HI + ml * 80 + kp * 8) = *(uint2*)&hi;
            *(uint2*)(smem + A_LO + ml * 80 + kp * 8) = *(uint2*)&lo;
        }
        // B: 64 rows x 32 bf16 hi+lo; 1 uint4 each per thread
        {
            int r = tid >> 2, kp = tid & 3;
            *(uint4*)(smem + B_HI + r * 80 + kp * 16) = *(const uint4*)&g_w1b_hi[r * 256 + kc + kp * 8];
            *(uint4*)(smem + B_LO + r * 80 + kp * 16) = *(const uint4*)&g_w1b_lo[r * 256 + kc + kp * 8];
        }
        __syncthreads();
        warp_mma16(sb + A_HI, sb + A_LO, sb + B_HI, sb + B_LO, mrow0, 0, lane, acc);
    }
    __syncthreads();
    float* C = (float*)smem;  // [128][65]
    {
        int g = lane >> 2, t2 = (lane & 3) * 2;
#pragma unroll
        for (int nf = 0; nf < 8; nf++) {
            int c = nf * 8 + t2;
            C[(mrow0 + g) * 65 + c] = acc[nf][0];
            C[(mrow0 + g) * 65 + c + 1] = acc[nf][1];
            C[(mrow0 + g + 8) * 65 + c] = acc[nf][2];
            C[(mrow0 + g + 8) * 65 + c + 1] = acc[nf][3];
        }
    }
    __syncthreads();
    if (tid < 128) {
        float v[64];
        float s = 0.f, s2 = 0.f;
#pragma unroll
        for (int c = 0; c < 64; c++) {
            v[c] = C[tid * 65 + c] + cb[c];
            s += v[c]; s2 += v[c] * v[c];
        }
        float mean = s * (1.f / 64.f);
        float inv = rsqrtf(s2 * (1.f / 64.f) - mean * mean + 1e-5f);
        size_t base = (size_t)(m0 + tid) * 64;
#pragma unroll
        for (int g4 = 0; g4 < 16; g4++) {
            float4 o;
            float* po = &o.x;
#pragma unroll
            for (int t = 0; t < 4; t++) {
                int c = g4 * 4 + t;
                float y = (v[c] - mean) * inv * lg[c] + lb[c];
                po[t] = gelu_exact(y);
            }
            *(float4*)&g_h1[base + g4 * 4] = o;
        }
    }
}

// ============================ conv2 via mma: M=16384 K=1024 N=256 (raw out) ============================
// Clone of validated fc_mma geometry: BM=64, BN=128, 8 warps as 4(m) x 2(n).
__global__ __launch_bounds__(256, 1) void conv2_mma() {
    __shared__ __align__(16) char smem[30720];
    const uint32_t sb = smem_u32(smem);
    const int tid = threadIdx.x, lane = tid & 31, w = tid >> 5;
    const int n0 = blockIdx.x * 128, m0 = blockIdx.y * 64;
    const int mrow0 = (w >> 1) * 16, ncol0 = (w & 1) * 64;
    constexpr int A_HI = 0, A_LO = 5120, B_HI = 10240, B_LO = 20480;

    float acc[8][4];
#pragma unroll
    for (int b = 0; b < 8; b++)
#pragma unroll
        for (int c = 0; c < 4; c++) acc[b][c] = 0.f;

    for (int kc = 0; kc < 1024; kc += 32) {
        __syncthreads();
        // A: 64 rows x 32 fp32 from g_h1 patches; 512 float4; 2 per thread
#pragma unroll
        for (int q = 0; q < 2; q++) {
            int idx = tid * 2 + q;
            int ml = idx >> 3, kp = idx & 7;
            int m = m0 + ml;
            int bt = m >> 4, ij = m & 15, oi = ij >> 2, oj = ij & 3;
            int k = kc + kp * 4;
            int kh = k >> 8, ko = k & 255;
            float4 v = *(const float4*)&g_h1[(size_t)bt * 16384 + (4 * oi + kh) * 1024 + oj * 256 + ko];
            float f[4] = {v.x, v.y, v.z, v.w};
            BF4 hi, lo;
#pragma unroll
            for (int t = 0; t < 4; t++) {
                hi.h[t] = __float2bfloat16(f[t]);
                lo.h[t] = __float2bfloat16(f[t] - __bfloat162float(hi.h[t]));
            }
            *(uint2*)(smem + A_HI + ml * 80 + kp * 8) = *(uint2*)&hi;
            *(uint2*)(smem + A_LO + ml * 80 + kp * 8) = *(uint2*)&lo;
        }
        // B: 128 rows x 32 bf16 hi+lo; 512 uint4 each; 2 per thread
#pragma unroll
        for (int it = 0; it < 2; it++) {
            int idx = tid + it * 256;
            int r = idx >> 2, kp = idx & 3;
            size_t src = (size_t)(n0 + r) * 1024 + kc + kp * 8;
            *(uint4*)(smem + B_HI + r * 80 + kp * 16) = *(const uint4*)&g_w2b_hi[src];
            *(uint4*)(smem + B_LO + r * 80 + kp * 16) = *(const uint4*)&g_w2b_lo[src];
        }
        __syncthreads();
        warp_mma16(sb + A_HI, sb + A_LO, sb + B_HI, sb + B_LO, mrow0, ncol0, lane, acc);
    }
    // raw fp32 out -> g_c2 (LN needs full row; done in ln2_kernel)
    int g = lane >> 2, t2 = (lane & 3) * 2;
    int row = m0 + mrow0 + g;
#pragma unroll
    for (int nf = 0; nf < 8; nf++) {
        int col = n0 + ncol0 + nf * 8 + t2;
        *(float2*)&g_c2[(size_t)row * 256 + col] = make_float2(acc[nf][0], acc[nf][1]);
        *(float2*)&g_c2[(size_t)(row + 8) * 256 + col] = make_float2(acc[nf][2], acc[nf][3]);
    }
}

// ---- ln2: bias + LN + GELU over 256-col rows; warp per row ----
__global__ __launch_bounds__(256) void ln2_kernel(
    const float* __restrict__ cb, const float* __restrict__ lg, const float* __restrict__ lb) {
    const int lane = threadIdx.x & 31, w = threadIdx.x >> 5;
    const int row = blockIdx.x * 8 + w;
    const int c0 = lane * 8;
    float v[8];
    float4 a = *(const float4*)&g_c2[(size_t)row * 256 + c0];
    float4 b = *(const float4*)&g_c2[(size_t)row * 256 + c0 + 4];
    float4 ba = *(const float4*)&cb[c0];
    float4 bb = *(const float4*)&cb[c0 + 4];
    v[0] = a.x + ba.x; v[1] = a.y + ba.y; v[2] = a.z + ba.z; v[3] = a.w + ba.w;
    v[4] = b.x + bb.x; v[5] = b.y + bb.y; v[6] = b.z + bb.z; v[7] = b.w + bb.w;
    float s = 0.f, s2 = 0.f;
#pragma unroll
    for (int t = 0; t < 8; t++) { s += v[t]; s2 += v[t] * v[t]; }
#pragma unroll
    for (int d = 16; d > 0; d >>= 1) {
        s += __shfl_xor_sync(0xffffffff, s, d);
        s2 += __shfl_xor_sync(0xffffffff, s2, d);
    }
    float mean = s * (1.f / 256.f);
    float inv = rsqrtf(s2 * (1.f / 256.f) - mean * mean + 1e-5f);
    float4 lga = *(const float4*)&lg[c0];
    float4 lgb = *(const float4*)&lg[c0 + 4];
    float4 lba = *(const float4*)&lb[c0];
    float4 lbb = *(const float4*)&lb[c0 + 4];
    float gm[8] = {lga.x, lga.y, lga.z, lga.w, lgb.x, lgb.y, lgb.z, lgb.w};
    float bt[8] = {lba.x, lba.y, lba.z, lba.w, lbb.x, lbb.y, lbb.z, lbb.w};
    float4 o0, o1;
    float* p0 = &o0.x; float* p1 = &o1.x;
#pragma unroll
    for (int t = 0; t < 4; t++) p0[t] = gelu_exact((v[t] - mean) * inv * gm[t] + bt[t]);
#pragma unroll
    for (int t = 4; t < 8; t++) p1[t - 4] = gelu_exact((v[t] - mean) * inv * gm[t] + bt[t]);
    *(float4*)&g_h2[(size_t)row * 256 + c0] = o0;       // g_h2 viewed as [16384][256] == [1024][4096]
    *(float4*)&g_h2[(size_t)row * 256 + c0 + 4] = o1;
}

// ============================ fc via mma (verbatim from passing R9) ============================
__global__ __launch_bounds__(256, 1) void fc_mma(const float* __restrict__ fb) {
    __shared__ __align__(16) char smem[30720];
    const uint32_t sb = smem_u32(smem);
    const int tid = threadIdx.x, lane = tid & 31, w = tid >> 5;
    const int n0 = blockIdx.x * 128, m0 = blockIdx.y * 64;
    const int mrow0 = (w >> 1) * 16, ncol0 = (w & 1) * 64;
    constexpr int A_HI = 0, A_LO = 5120, B_HI = 10240, B_LO = 20480;

    float acc[8][4];
#pragma unroll
    for (int b = 0; b < 8; b++)
#pragma unroll
        for (int c = 0; c < 4; c++) acc[b][c] = 0.f;

    for (int kc = 0; kc < 4096; kc += 32) {
        __syncthreads();
#pragma unroll
        for (int q = 0; q < 2; q++) {
            int idx = tid * 2 + q;
            int ml = idx >> 3, kp = idx & 7;
            float4 v = *(const float4*)&g_h2[(size_t)(m0 + ml) * 4096 + kc + kp * 4];
            float f[4] = {v.x, v.y, v.z, v.w};
            BF4 hi, lo;
#pragma unroll
            for (int t = 0; t < 4; t++) {
                hi.h[t] = __float2bfloat16(f[t]);
                lo.h[t] = __float2bfloat16(f[t] - __bfloat162float(hi.h[t]));
            }
            *(uint2*)(smem + A_HI + ml * 80 + kp * 8) = *(uint2*)&hi;
            *(uint2*)(smem + A_LO + ml * 80 + kp * 8) = *(uint2*)&lo;
        }
#pragma unroll
        for (int it = 0; it < 2; it++) {
            int idx = tid + it * 256;
            int r = idx >> 2, kp = idx & 3;
            size_t src = (size_t)(n0 + r) * 4096 + kc + kp * 8;
            *(uint4*)(smem + B_HI + r * 80 + kp * 16) = *(const uint4*)&g_fwb_hi[src];
            *(uint4*)(smem + B_LO + r * 80 + kp * 16) = *(const uint4*)&g_fwb_lo[src];
        }
        __syncthreads();
        warp_mma16(sb + A_HI, sb + A_LO, sb + B_HI, sb + B_LO, mrow0, ncol0, lane, acc);
    }
    int g = lane >> 2, t2 = (lane & 3) * 2;
    int row = m0 + mrow0 + g;
#pragma unroll
    for (int nf = 0; nf < 8; nf++) {
        int col = n0 + ncol0 + nf * 8 + t2;
        float2 b01 = *(const float2*)&fb[col];
        *(float2*)&g_emb[(size_t)row * 512 + col] =
            make_float2(acc[nf][0] + b01.x, acc[nf][1] + b01.y);
        *(float2*)&g_emb[(size_t)(row + 8) * 512 + col] =
            make_float2(acc[nf][2] + b01.x, acc[nf][3] + b01.y);
    }
}

// ============================ Fourier gating (verbatim, passing) ============================
__global__ __launch_bounds__(128) void gate_kernel(const float* __restrict__ w_gate) {
    const int b = blockIdx.x;
    const int tid = threadIdx.x;
    __shared__ float cs[8][16], sn[8][16];
    __shared__ float lgs[6];
    {
        int f = tid >> 4, t = tid & 15;
        float ang = -6.28318530717958647692f * (float)(f + 1) * (float)t * (1.f / 16.f);
        cs[f][t] = cosf(ang);
        sn[f][t] = sinf(ang);
    }
    if (tid < 6) lgs[tid] = 0.f;
    __syncthreads();
    float part[6] = {0.f, 0.f, 0.f, 0.f, 0.f, 0.f};
    for (int d = tid; d < 512; d += 128) {
        float v[16];
#pragma unroll
        for (int t = 0; t < 16; t++) v[t] = g_emb[(b * 16 + t) * 512 + d];
#pragma unroll
        for (int f = 0; f < 8; f++) {
            float re = 0.f, im = 0.f;
#pragma unroll
            for (int t = 0; t < 16; t++) {
                re = fmaf(v[t], cs[f][t], re);
                im = fmaf(v[t], sn[f][t], im);
            }
            float amp = sqrtf(re * re + im * im) * 0.25f;
#pragma unroll
            for (int e = 0; e < 6; e++) part[e] = fmaf(amp, w_gate[f * 6 + e], part[e]);
        }
    }
#pragma unroll
    for (int e = 0; e < 6; e++) atomicAdd(&lgs[e], part[e]);
    __syncthreads();
    if (tid == 0) {
        float wv[6];
#pragma unroll
        for (int e = 0; e < 6; e++) wv[e] = lgs[e] * (1.f / 512.f);
        int i1 = 0;
        for (int e = 1; e < 6; e++) if (wv[e] > wv[i1]) i1 = e;
        int i2 = -1;
        for (int e = 0; e < 6; e++) {
            if (e == i1) continue;
            if (i2 < 0 || wv[e] > wv[i2]) i2 = e;
        }
        float e2 = expf(wv[i2] - wv[i1]);
        float s = 1.f + e2;
#pragma unroll
        for (int e = 0; e < 6; e++) g_gates[b * 6 + e] = 0.f;
        g_gates[b * 6 + i1] = 1.f / s;
        g_gates[b * 6 + i2] = e2 / s;
    }
}

// ============================ experts (verbatim, passing) ============================
__global__ __launch_bounds__(256) void expert_kernel(
    const float* __restrict__ ew, const float* __restrict__ eb, float* __restrict__ out) {
    __shared__ float As[32][16];
    __shared__ float Bs[32][128];
    const int tid = threadIdx.x;
    const int tx = tid & 15, ty = tid >> 4;
    const int b = blockIdx.y;
    const int fx = blockIdx.x * 128;
    float comb[8];
#pragma unroll
    for (int c = 0; c < 8; c++) comb[c] = 0.f;

    for (int e = 0; e < 6; e++) {
        float gv = g_gates[b * 6 + e];
        if (gv == 0.f) continue;
        float acc[8];
#pragma unroll
        for (int c = 0; c < 8; c++) acc[c] = 0.f;
        for (int kc = 0; kc < 512; kc += 32) {
            if (tid < 128) {
                int ml = tid >> 3, k4 = (tid & 7) * 4;
                float4 v = *(const float4*)&g_emb[(b * 16 + ml) * 512 + kc + k4];
                As[k4 + 0][ml] = v.x; As[k4 + 1][ml] = v.y;
                As[k4 + 2][ml] = v.z; As[k4 + 3][ml] = v.w;
            }
#pragma unroll
            for (int q = 0; q < 4; q++) {
                int vI = tid + q * 256;
                int kl = vI >> 5, n4 = (vI & 31) * 4;
                *(float4*)&Bs[kl][n4] = *(const float4*)&ew[(e * 512 + kc + kl) * 512 + fx + n4];
            }
            __syncthreads();
#pragma unroll
            for (int k = 0; k < 32; k++) {
                float a = As[k][ty];
                float4 b0 = *(const float4*)&Bs[k][tx * 8];
                float4 b1 = *(const float4*)&Bs[k][tx * 8 + 4];
                acc[0] = fmaf(a, b0.x, acc[0]);
                acc[1] = fmaf(a, b0.y, acc[1]);
                acc[2] = fmaf(a, b0.z, acc[2]);
                acc[3] = fmaf(a, b0.w, acc[3]);
                acc[4] = fmaf(a, b1.x, acc[4]);
                acc[5] = fmaf(a, b1.y, acc[5]);
                acc[6] = fmaf(a, b1.z, acc[6]);
                acc[7] = fmaf(a, b1.w, acc[7]);
            }
            __syncthreads();
        }
#pragma unroll
        for (int c = 0; c < 8; c++) {
            float z = acc[c] + eb[e * 512 + fx + tx * 8 + c];
            comb[c] = fmaf(gv, expf(z), comb[c]);
        }
    }
#pragma unroll
    for (int c = 0; c < 8; c++) {
        float v = comb[c];
        if (v == 0.f) v = 2.220446049250313e-16f;
        out[(b * 16 + ty) * 512 + fx + tx * 8 + c] = logf(v);
    }
}

// ============================ launch ============================
extern "C" void kernel_launch(void* const* d_in, const int* in_sizes, int n_in,
                              void* d_out, int out_size) {
    const float* x       = (const float*)d_in[0];
    const float* conv1_w = (const float*)d_in[1];
    const float* conv1_b = (const float*)d_in[2];
    const float* ln1_g   = (const float*)d_in[3];
    const float* ln1_b   = (const float*)d_in[4];
    const float* conv2_w = (const float*)d_in[5];
    const float* conv2_b = (const float*)d_in[6];
    const float* ln2_g   = (const float*)d_in[7];
    const float* ln2_b   = (const float*)d_in[8];
    const float* fc_w    = (const float*)d_in[9];
    const float* fc_b    = (const float*)d_in[10];
    const float* w_gate  = (const float*)d_in[11];
    const float* exp_w   = (const float*)d_in[12];
    const float* exp_b   = (const float*)d_in[13];
    float* out = (float*)d_out;

    prep_kernel<<<1024, 256>>>(conv1_w, conv2_w);
    transpose_cvt<<<dim3(16, 128), dim3(32, 8)>>>(fc_w);
    conv1_mma<<<2048, 256>>>(x, conv1_b, ln1_g, ln1_b);
    conv2_mma<<<dim3(2, 256), 256>>>();
    ln2_kernel<<<2048, 256>>>(conv2_b, ln2_g, ln2_b);
    fc_mma<<<dim3(4, 16), 256>>>(fc_b);
    gate_kernel<<<64, 128>>>(w_gate);
    expert_kernel<<<dim3(4, 64), 256>>>(exp_w, exp_b, out);
}

// round 12
// speedup vs baseline: 1.4204x; 1.0915x over previous
#include <cuda_runtime.h>
#include <cuda_bf16.h>
#include <cstdint>
#include <math.h>

// ============================ scratch (same as passing R10) ============================
__device__ __align__(16) float g_h1[16777216];   // (1024,16,16,64) conv1 out
__device__ __align__(16) float g_c2[4194304];    // conv2 raw GEMM out (16384,256)
__device__ __align__(16) float g_h2[4194304];    // (1024,4096) fc A
__device__ __align__(16) float g_emb[524288];    // (1024,512)
__device__ __align__(16) float g_gates[384];     // (64,6)
__device__ __align__(16) __nv_bfloat16 g_w1b_hi[16384],   g_w1b_lo[16384];    // [64][256]
__device__ __align__(16) __nv_bfloat16 g_w2b_hi[262144],  g_w2b_lo[262144];   // [256][1024]
__device__ __align__(16) __nv_bfloat16 g_fwb_hi[2097152], g_fwb_lo[2097152];  // [512][4096]

// ============================ MMA helpers (validated) ============================
__device__ __forceinline__ uint32_t smem_u32(const void* p) {
    uint32_t a;
    asm("{ .reg .u64 t; cvta.to.shared.u64 t, %1; cvt.u32.u64 %0, t; }" : "=r"(a) : "l"(p));
    return a;
}
__device__ __forceinline__ void ldsm4(uint32_t r[4], uint32_t a) {
    asm volatile("ldmatrix.sync.aligned.m8n8.x4.shared.b16 {%0,%1,%2,%3}, [%4];"
                 : "=r"(r[0]), "=r"(r[1]), "=r"(r[2]), "=r"(r[3]) : "r"(a));
}
__device__ __forceinline__ void mma16816(float c[4], const uint32_t a[4], const uint32_t b[2]) {
    asm volatile(
        "mma.sync.aligned.m16n8k16.row.col.f32.bf16.bf16.f32 "
        "{%0,%1,%2,%3}, {%4,%5,%6,%7}, {%8,%9}, {%0,%1,%2,%3};"
        : "+f"(c[0]), "+f"(c[1]), "+f"(c[2]), "+f"(c[3])
        : "r"(a[0]), "r"(a[1]), "r"(a[2]), "r"(a[3]), "r"(b[0]), "r"(b[1]));
}
struct __align__(8)  BF4 { __nv_bfloat16 h[4]; };

__device__ __forceinline__ float gelu_exact(float y) {
    return 0.5f * y * (1.f + erff(y * 0.70710678118654752440f));
}
__device__ __forceinline__ void split4(const float4 v, BF4& hi, BF4& lo) {
    float f[4] = {v.x, v.y, v.z, v.w};
#pragma unroll
    for (int t = 0; t < 4; t++) {
        hi.h[t] = __float2bfloat16(f[t]);
        lo.h[t] = __float2bfloat16(f[t] - __bfloat162float(hi.h[t]));
    }
}

// warp tile 16x64, one BK=32 chunk, hi/lo split. SMEM rows 80B stride. (validated)
__device__ __forceinline__ void warp_mma16(
    uint32_t aHi, uint32_t aLo, uint32_t bHi, uint32_t bLo,
    int mrow0, int ncol0, int lane, float acc[8][4]) {
#pragma unroll
    for (int ks = 0; ks < 2; ks++) {
        const int k0 = ks * 16;
        uint32_t ah[4], al[4];
        {
            uint32_t ro = (uint32_t)((mrow0 + (lane & 15)) * 80 + (k0 + (lane >> 4) * 8) * 2);
            ldsm4(ah, aHi + ro);
            ldsm4(al, aLo + ro);
        }
        uint32_t bh[8][2], bl[8][2];
#pragma unroll
        for (int np = 0; np < 4; np++) {
            uint32_t ro = (uint32_t)((ncol0 + np * 16 + (lane & 7) + ((lane >> 4) * 8)) * 80 +
                                     (k0 + ((lane >> 3) & 1) * 8) * 2);
            uint32_t t[4];
            ldsm4(t, bHi + ro);
            bh[np * 2][0] = t[0]; bh[np * 2][1] = t[1];
            bh[np * 2 + 1][0] = t[2]; bh[np * 2 + 1][1] = t[3];
            ldsm4(t, bLo + ro);
            bl[np * 2][0] = t[0]; bl[np * 2][1] = t[1];
            bl[np * 2 + 1][0] = t[2]; bl[np * 2 + 1][1] = t[3];
        }
#pragma unroll
        for (int nf = 0; nf < 8; nf++) {
            mma16816(acc[nf], ah, bh[nf]);
            mma16816(acc[nf], ah, bl[nf]);
            mma16816(acc[nf], al, bh[nf]);
        }
    }
}

// ============================ weight prep (verbatim R10) ============================
__global__ __launch_bounds__(256) void prep_kernel(const float* __restrict__ w1,
                                                   const float* __restrict__ w2) {
    int idx = blockIdx.x * 256 + threadIdx.x;
    if (idx < 16384) {
        int n = idx >> 8, k = idx & 255;
        int kh = k >> 6, kw = (k >> 4) & 3, ci = k & 15;
        float v = w1[n * 256 + ci * 16 + kh * 4 + kw];
        __nv_bfloat16 h = __float2bfloat16(v);
        g_w1b_hi[idx] = h;
        g_w1b_lo[idx] = __float2bfloat16(v - __bfloat162float(h));
    }
    if (idx < 262144) {
        int n = idx >> 10, k = idx & 1023;
        int kh = k >> 8, kw = (k >> 6) & 3, ci = k & 63;
        float v = w2[n * 1024 + ci * 16 + kh * 4 + kw];
        __nv_bfloat16 h = __float2bfloat16(v);
        g_w2b_hi[idx] = h;
        g_w2b_lo[idx] = __float2bfloat16(v - __bfloat162float(h));
    }
}

// fc_w fp32 [4096][512] -> bf16 hi/lo [512][4096] (verbatim R10)
__global__ __launch_bounds__(256) void transpose_cvt(const float* __restrict__ src) {
    __shared__ float tile[32][33];
    int c0 = blockIdx.x * 32, r0 = blockIdx.y * 32;
#pragma unroll
    for (int q = 0; q < 4; q++)
        tile[threadIdx.y + q * 8][threadIdx.x] =
            src[(size_t)(r0 + threadIdx.y + q * 8) * 512 + c0 + threadIdx.x];
    __syncthreads();
#pragma unroll
    for (int q = 0; q < 4; q++) {
        int c = c0 + threadIdx.y + q * 8;
        float v = tile[threadIdx.x][threadIdx.y + q * 8];
        __nv_bfloat16 h = __float2bfloat16(v);
        g_fwb_hi[(size_t)c * 4096 + r0 + threadIdx.x] = h;
        g_fwb_lo[(size_t)c * 4096 + r0 + threadIdx.x] =
            __float2bfloat16(v - __bfloat162float(h));
    }
}

// ============================ conv1 (R10 + register-prefetch pipelining) ============================
__global__ __launch_bounds__(256, 1) void conv1_mma(
    const float* __restrict__ x, const float* __restrict__ cb,
    const float* __restrict__ lg, const float* __restrict__ lb) {
    __shared__ __align__(16) char smem[33280];
    const uint32_t sb = smem_u32(smem);
    const int tid = threadIdx.x, lane = tid & 31, w = tid >> 5;
    const int m0 = blockIdx.x * 128;
    constexpr int A_HI = 0, A_LO = 10240, B_HI = 20480, B_LO = 25600;
    const int mrow0 = w * 16;

    float acc[8][4];
#pragma unroll
    for (int b = 0; b < 8; b++)
#pragma unroll
        for (int c = 0; c < 4; c++) acc[b][c] = 0.f;

    const int br = tid >> 2, bkp = tid & 3;
    float4 ra[4];
    uint4 rbh, rbl;

    // prefetch chunk 0
#pragma unroll
    for (int q = 0; q < 4; q++) {
        int idx = tid * 4 + q;
        int ml = idx >> 3, kp = idx & 7;
        int m = m0 + ml;
        int bt = m >> 8, ij = m & 255, i = ij >> 4, j = ij & 15;
        int k = kp * 4;
        int kh = k >> 6, ko = k & 63;
        ra[q] = *(const float4*)&x[(size_t)bt * 65536 + (4 * i + kh) * 1024 + j * 64 + ko];
    }
    rbh = *(const uint4*)&g_w1b_hi[br * 256 + bkp * 8];
    rbl = *(const uint4*)&g_w1b_lo[br * 256 + bkp * 8];

    for (int ch = 0; ch < 8; ch++) {
        __syncthreads();
        // store regs -> smem
#pragma unroll
        for (int q = 0; q < 4; q++) {
            int idx = tid * 4 + q;
            int ml = idx >> 3, kp = idx & 7;
            BF4 hi, lo;
            split4(ra[q], hi, lo);
            *(uint2*)(smem + A_HI + ml * 80 + kp * 8) = *(uint2*)&hi;
            *(uint2*)(smem + A_LO + ml * 80 + kp * 8) = *(uint2*)&lo;
        }
        *(uint4*)(smem + B_HI + br * 80 + bkp * 16) = rbh;
        *(uint4*)(smem + B_LO + br * 80 + bkp * 16) = rbl;
        // prefetch next chunk
        if (ch < 7) {
            const int kc = (ch + 1) * 32;
#pragma unroll
            for (int q = 0; q < 4; q++) {
                int idx = tid * 4 + q;
                int ml = idx >> 3, kp = idx & 7;
                int m = m0 + ml;
                int bt = m >> 8, ij = m & 255, i = ij >> 4, j = ij & 15;
                int k = kc + kp * 4;
                int kh = k >> 6, ko = k & 63;
                ra[q] = *(const float4*)&x[(size_t)bt * 65536 + (4 * i + kh) * 1024 + j * 64 + ko];
            }
            rbh = *(const uint4*)&g_w1b_hi[br * 256 + kc + bkp * 8];
            rbl = *(const uint4*)&g_w1b_lo[br * 256 + kc + bkp * 8];
        }
        __syncthreads();
        warp_mma16(sb + A_HI, sb + A_LO, sb + B_HI, sb + B_LO, mrow0, 0, lane, acc);
    }
    __syncthreads();
    float* C = (float*)smem;  // [128][65]
    {
        int g = lane >> 2, t2 = (lane & 3) * 2;
#pragma unroll
        for (int nf = 0; nf < 8; nf++) {
            int c = nf * 8 + t2;
            C[(mrow0 + g) * 65 + c] = acc[nf][0];
            C[(mrow0 + g) * 65 + c + 1] = acc[nf][1];
            C[(mrow0 + g + 8) * 65 + c] = acc[nf][2];
            C[(mrow0 + g + 8) * 65 + c + 1] = acc[nf][3];
        }
    }
    __syncthreads();
    if (tid < 128) {
        float v[64];
        float s = 0.f, s2 = 0.f;
#pragma unroll
        for (int c = 0; c < 64; c++) {
            v[c] = C[tid * 65 + c] + cb[c];
            s += v[c]; s2 += v[c] * v[c];
        }
        float mean = s * (1.f / 64.f);
        float inv = rsqrtf(s2 * (1.f / 64.f) - mean * mean + 1e-5f);
        size_t base = (size_t)(m0 + tid) * 64;
#pragma unroll
        for (int g4 = 0; g4 < 16; g4++) {
            float4 o;
            float* po = &o.x;
#pragma unroll
            for (int t = 0; t < 4; t++) {
                int c = g4 * 4 + t;
                po[t] = gelu_exact((v[c] - mean) * inv * lg[c] + lb[c]);
            }
            *(float4*)&g_h1[base + g4 * 4] = o;
        }
    }
}

// ============================ pipelined BM=64 x BN=128 load helpers ============================
// MODE 0: linear A rows; MODE 1: conv2 patch gather from g_h1.
template <int MODE>
__device__ __forceinline__ void ldA2(const float* __restrict__ Af, size_t a_row0,
                                     size_t a_stride, int tid, int kc, float4 ra[2]) {
#pragma unroll
    for (int q = 0; q < 2; q++) {
        int idx = tid * 2 + q;
        int ml = idx >> 3, kp = idx & 7;
        if (MODE == 0) {
            ra[q] = *(const float4*)&Af[(a_row0 + ml) * a_stride + kc + kp * 4];
        } else {
            int m = (int)a_row0 + ml;
            int bt = m >> 4, ij = m & 15, oi = ij >> 2, oj = ij & 3;
            int k = kc + kp * 4;
            int kh = k >> 8, ko = k & 255;
            ra[q] = *(const float4*)&g_h1[(size_t)bt * 16384 + (4 * oi + kh) * 1024 + oj * 256 + ko];
        }
    }
}
__device__ __forceinline__ void ldB2(const __nv_bfloat16* __restrict__ Bhi,
                                     const __nv_bfloat16* __restrict__ Blo,
                                     size_t b_row0, size_t b_stride, int tid, int kc,
                                     uint4 rbh[2], uint4 rbl[2]) {
#pragma unroll
    for (int it = 0; it < 2; it++) {
        int idx = tid + it * 256;
        int r = idx >> 2, kp = idx & 3;
        size_t src = (b_row0 + r) * b_stride + kc + kp * 8;
        rbh[it] = *(const uint4*)&Bhi[src];
        rbl[it] = *(const uint4*)&Blo[src];
    }
}
__device__ __forceinline__ void stAB2(char* smem, int tid, const float4 ra[2],
                                      const uint4 rbh[2], const uint4 rbl[2]) {
    constexpr int A_HI = 0, A_LO = 5120, B_HI = 10240, B_LO = 20480;
#pragma unroll
    for (int q = 0; q < 2; q++) {
        int idx = tid * 2 + q;
        int ml = idx >> 3, kp = idx & 7;
        BF4 hi, lo;
        split4(ra[q], hi, lo);
        *(uint2*)(smem + A_HI + ml * 80 + kp * 8) = *(uint2*)&hi;
        *(uint2*)(smem + A_LO + ml * 80 + kp * 8) = *(uint2*)&lo;
    }
#pragma unroll
    for (int it = 0; it < 2; it++) {
        int idx = tid + it * 256;
        int r = idx >> 2, kp = idx & 3;
        *(uint4*)(smem + B_HI + r * 80 + kp * 16) = rbh[it];
        *(uint4*)(smem + B_LO + r * 80 + kp * 16) = rbl[it];
    }
}

template <int NCH, int MODE>
__device__ __forceinline__ void gemm64x128_pipe(
    char* smem, uint32_t sb, int tid, int lane, int mrow0, int ncol0,
    const float* __restrict__ Af, size_t a_row0, size_t a_stride,
    const __nv_bfloat16* __restrict__ Bhi, const __nv_bfloat16* __restrict__ Blo,
    size_t b_row0, size_t b_stride, float acc[8][4]) {
    constexpr int A_HI = 0, A_LO = 5120, B_HI = 10240, B_LO = 20480;
    float4 ra[2];
    uint4 rbh[2], rbl[2];
    ldA2<MODE>(Af, a_row0, a_stride, tid, 0, ra);
    ldB2(Bhi, Blo, b_row0, b_stride, tid, 0, rbh, rbl);
    for (int ch = 0; ch < NCH; ch++) {
        __syncthreads();
        stAB2(smem, tid, ra, rbh, rbl);
        if (ch + 1 < NCH) {
            ldA2<MODE>(Af, a_row0, a_stride, tid, (ch + 1) * 32, ra);
            ldB2(Bhi, Blo, b_row0, b_stride, tid, (ch + 1) * 32, rbh, rbl);
        }
        __syncthreads();
        warp_mma16(sb + A_HI, sb + A_LO, sb + B_HI, sb + B_LO, mrow0, ncol0, lane, acc);
    }
}

#define INIT_ACC8(acc) \
    _Pragma("unroll") for (int _b = 0; _b < 8; _b++) \
    _Pragma("unroll") for (int _c = 0; _c < 4; _c++) acc[_b][_c] = 0.f;

// ---- conv2: M=16384 K=1024 N=256 raw -> g_c2; grid (2,256) ----
__global__ __launch_bounds__(256, 1) void conv2_mma() {
    __shared__ __align__(16) char smem[30720];
    const uint32_t sb = smem_u32(smem);
    const int tid = threadIdx.x, lane = tid & 31, w = tid >> 5;
    const int n0 = blockIdx.x * 128, m0 = blockIdx.y * 64;
    const int mrow0 = (w >> 1) * 16, ncol0 = (w & 1) * 64;
    float acc[8][4];
    INIT_ACC8(acc);
    gemm64x128_pipe<32, 1>(smem, sb, tid, lane, mrow0, ncol0,
                           nullptr, (size_t)m0, 0,
                           g_w2b_hi, g_w2b_lo, (size_t)n0, 1024, acc);
    int g = lane >> 2, t2 = (lane & 3) * 2;
    int row = m0 + mrow0 + g;
#pragma unroll
    for (int nf = 0; nf < 8; nf++) {
        int col = n0 + ncol0 + nf * 8 + t2;
        *(float2*)&g_c2[(size_t)row * 256 + col] = make_float2(acc[nf][0], acc[nf][1]);
        *(float2*)&g_c2[(size_t)(row + 8) * 256 + col] = make_float2(acc[nf][2], acc[nf][3]);
    }
}

// ---- ln2 (verbatim R10) ----
__global__ __launch_bounds__(256) void ln2_kernel(
    const float* __restrict__ cb, const float* __restrict__ lg, const float* __restrict__ lb) {
    const int lane = threadIdx.x & 31, w = threadIdx.x >> 5;
    const int row = blockIdx.x * 8 + w;
    const int c0 = lane * 8;
    float v[8];
    float4 a = *(const float4*)&g_c2[(size_t)row * 256 + c0];
    float4 b = *(const float4*)&g_c2[(size_t)row * 256 + c0 + 4];
    float4 ba = *(const float4*)&cb[c0];
    float4 bb = *(const float4*)&cb[c0 + 4];
    v[0] = a.x + ba.x; v[1] = a.y + ba.y; v[2] = a.z + ba.z; v[3] = a.w + ba.w;
    v[4] = b.x + bb.x; v[5] = b.y + bb.y; v[6] = b.z + bb.z; v[7] = b.w + bb.w;
    float s = 0.f, s2 = 0.f;
#pragma unroll
    for (int t = 0; t < 8; t++) { s += v[t]; s2 += v[t] * v[t]; }
#pragma unroll
    for (int d = 16; d > 0; d >>= 1) {
        s += __shfl_xor_sync(0xffffffff, s, d);
        s2 += __shfl_xor_sync(0xffffffff, s2, d);
    }
    float mean = s * (1.f / 256.f);
    float inv = rsqrtf(s2 * (1.f / 256.f) - mean * mean + 1e-5f);
    float4 lga = *(const float4*)&lg[c0];
    float4 lgb = *(const float4*)&lg[c0 + 4];
    float4 lba = *(const float4*)&lb[c0];
    float4 lbb = *(const float4*)&lb[c0 + 4];
    float gm[8] = {lga.x, lga.y, lga.z, lga.w, lgb.x, lgb.y, lgb.z, lgb.w};
    float bt[8] = {lba.x, lba.y, lba.z, lba.w, lbb.x, lbb.y, lbb.z, lbb.w};
    float4 o0, o1;
    float* p0 = &o0.x; float* p1 = &o1.x;
#pragma unroll
    for (int t = 0; t < 4; t++) p0[t] = gelu_exact((v[t] - mean) * inv * gm[t] + bt[t]);
#pragma unroll
    for (int t = 4; t < 8; t++) p1[t - 4] = gelu_exact((v[t] - mean) * inv * gm[t] + bt[t]);
    *(float4*)&g_h2[(size_t)row * 256 + c0] = o0;
    *(float4*)&g_h2[(size_t)row * 256 + c0 + 4] = o1;
}

// ---- fc: M=1024 K=4096 N=512 + bias -> g_emb; grid (4,16) ----
__global__ __launch_bounds__(256, 1) void fc_mma(const float* __restrict__ fb) {
    __shared__ __align__(16) char smem[30720];
    const uint32_t sb = smem_u32(smem);
    const int tid = threadIdx.x, lane = tid & 31, w = tid >> 5;
    const int n0 = blockIdx.x * 128, m0 = blockIdx.y * 64;
    const int mrow0 = (w >> 1) * 16, ncol0 = (w & 1) * 64;
    float acc[8][4];
    INIT_ACC8(acc);
    gemm64x128_pipe<128, 0>(smem, sb, tid, lane, mrow0, ncol0,
                            g_h2, (size_t)m0, 4096,
                            g_fwb_hi, g_fwb_lo, (size_t)n0, 4096, acc);
    int g = lane >> 2, t2 = (lane & 3) * 2;
    int row = m0 + mrow0 + g;
#pragma unroll
    for (int nf = 0; nf < 8; nf++) {
        int col = n0 + ncol0 + nf * 8 + t2;
        float2 b01 = *(const float2*)&fb[col];
        *(float2*)&g_emb[(size_t)row * 512 + col] =
            make_float2(acc[nf][0] + b01.x, acc[nf][1] + b01.y);
        *(float2*)&g_emb[(size_t)(row + 8) * 512 + col] =
            make_float2(acc[nf][2] + b01.x, acc[nf][3] + b01.y);
    }
}

// ============================ Fourier gating (verbatim R10, g_gates) ============================
__global__ __launch_bounds__(128) void gate_kernel(const float* __restrict__ w_gate) {
    const int b = blockIdx.x;
    const int tid = threadIdx.x;
    __shared__ float cs[8][16], sn[8][16];
    __shared__ float lgs[6];
    {
        int f = tid >> 4, t = tid & 15;
        float ang = -6.28318530717958647692f * (float)(f + 1) * (float)t * (1.f / 16.f);
        cs[f][t] = cosf(ang);
        sn[f][t] = sinf(ang);
    }
    if (tid < 6) lgs[tid] = 0.f;
    __syncthreads();
    float part[6] = {0.f, 0.f, 0.f, 0.f, 0.f, 0.f};
    for (int d = tid; d < 512; d += 128) {
        float v[16];
#pragma unroll
        for (int t = 0; t < 16; t++) v[t] = g_emb[(b * 16 + t) * 512 + d];
#pragma unroll
        for (int f = 0; f < 8; f++) {
            float re = 0.f, im = 0.f;
#pragma unroll
            for (int t = 0; t < 16; t++) {
                re = fmaf(v[t], cs[f][t], re);
                im = fmaf(v[t], sn[f][t], im);
            }
            float amp = sqrtf(re * re + im * im) * 0.25f;
#pragma unroll
            for (int e = 0; e < 6; e++) part[e] = fmaf(amp, w_gate[f * 6 + e], part[e]);
        }
    }
#pragma unroll
    for (int e = 0; e < 6; e++) atomicAdd(&lgs[e], part[e]);
    __syncthreads();
    if (tid == 0) {
        float wv[6];
#pragma unroll
        for (int e = 0; e < 6; e++) wv[e] = lgs[e] * (1.f / 512.f);
        int i1 = 0;
        for (int e = 1; e < 6; e++) if (wv[e] > wv[i1]) i1 = e;
        int i2 = -1;
        for (int e = 0; e < 6; e++) {
            if (e == i1) continue;
            if (i2 < 0 || wv[e] > wv[i2]) i2 = e;
        }
        float e2 = expf(wv[i2] - wv[i1]);
        float s = 1.f + e2;
#pragma unroll
        for (int e = 0; e < 6; e++) g_gates[b * 6 + e] = 0.f;
        g_gates[b * 6 + i1] = 1.f / s;
        g_gates[b * 6 + i2] = e2 / s;
    }
}

// ============================ experts (verbatim R10, SIMT) ============================
__global__ __launch_bounds__(256) void expert_kernel(
    const float* __restrict__ ew, const float* __restrict__ eb, float* __restrict__ out) {
    __shared__ float As[32][16];
    __shared__ float Bs[32][128];
    const int tid = threadIdx.x;
    const int tx = tid & 15, ty = tid >> 4;
    const int b = blockIdx.y;
    const int fx = blockIdx.x * 128;
    float comb[8];
#pragma unroll
    for (int c = 0; c < 8; c++) comb[c] = 0.f;

    for (int e = 0; e < 6; e++) {
        float gv = g_gates[b * 6 + e];
        if (gv == 0.f) continue;
        float acc[8];
#pragma unroll
        for (int c = 0; c < 8; c++) acc[c] = 0.f;
        for (int kc = 0; kc < 512; kc += 32) {
            if (tid < 128) {
                int ml = tid >> 3, k4 = (tid & 7) * 4;
                float4 v = *(const float4*)&g_emb[(b * 16 + ml) * 512 + kc + k4];
                As[k4 + 0][ml] = v.x; As[k4 + 1][ml] = v.y;
                As[k4 + 2][ml] = v.z; As[k4 + 3][ml] = v.w;
            }
#pragma unroll
            for (int q = 0; q < 4; q++) {
                int vI = tid + q * 256;
                int kl = vI >> 5, n4 = (vI & 31) * 4;
                *(float4*)&Bs[kl][n4] = *(const float4*)&ew[(e * 512 + kc + kl) * 512 + fx + n4];
            }
            __syncthreads();
#pragma unroll
            for (int k = 0; k < 32; k++) {
                float a = As[k][ty];
                float4 b0 = *(const float4*)&Bs[k][tx * 8];
                float4 b1 = *(const float4*)&Bs[k][tx * 8 + 4];
                acc[0] = fmaf(a, b0.x, acc[0]);
                acc[1] = fmaf(a, b0.y, acc[1]);
                acc[2] = fmaf(a, b0.z, acc[2]);
                acc[3] = fmaf(a, b0.w, acc[3]);
                acc[4] = fmaf(a, b1.x, acc[4]);
                acc[5] = fmaf(a, b1.y, acc[5]);
                acc[6] = fmaf(a, b1.z, acc[6]);
                acc[7] = fmaf(a, b1.w, acc[7]);
            }
            __syncthreads();
        }
#pragma unroll
        for (int c = 0; c < 8; c++) {
            float z = acc[c] + eb[e * 512 + fx + tx * 8 + c];
            comb[c] = fmaf(gv, expf(z), comb[c]);
        }
    }
#pragma unroll
    for (int c = 0; c < 8; c++) {
        float v = comb[c];
        if (v == 0.f) v = 2.220446049250313e-16f;
        out[(b * 16 + ty) * 512 + fx + tx * 8 + c] = logf(v);
    }
}

// ============================ launch ============================
extern "C" void kernel_launch(void* const* d_in, const int* in_sizes, int n_in,
                              void* d_out, int out_size) {
    const float* x       = (const float*)d_in[0];
    const float* conv1_w = (const float*)d_in[1];
    const float* conv1_b = (const float*)d_in[2];
    const float* ln1_g   = (const float*)d_in[3];
    const float* ln1_b   = (const float*)d_in[4];
    const float* conv2_w = (const float*)d_in[5];
    const float* conv2_b = (const float*)d_in[6];
    const float* ln2_g   = (const float*)d_in[7];
    const float* ln2_b   = (const float*)d_in[8];
    const float* fc_w    = (const float*)d_in[9];
    const float* fc_b    = (const float*)d_in[10];
    const float* w_gate  = (const float*)d_in[11];
    const float* exp_w   = (const float*)d_in[12];
    const float* exp_b   = (const float*)d_in[13];
    float* out = (float*)d_out;

    prep_kernel<<<1024, 256>>>(conv1_w, conv2_w);
    transpose_cvt<<<dim3(16, 128), dim3(32, 8)>>>(fc_w);
    conv1_mma<<<2048, 256>>>(x, conv1_b, ln1_g, ln1_b);
    conv2_mma<<<dim3(2, 256), 256>>>();
    ln2_kernel<<<2048, 256>>>(conv2_b, ln2_g, ln2_b);
    fc_mma<<<dim3(4, 16), 256>>>(fc_b);
    gate_kernel<<<64, 128>>>(w_gate);
    expert_kernel<<<dim3(4, 64), 256>>>(exp_w, exp_b, out);
}

// round 16
// speedup vs baseline: 1.7419x; 1.2263x over previous
#include <cuda_runtime.h>
#include <cuda_bf16.h>
#include <cstdint>
#include <math.h>

// ============================ scratch ============================
__device__ __align__(16) float g_h1[16777216];   // (1024,16,16,64) conv1 out
__device__ __align__(16) float g_c2[4194304];    // conv2 raw GEMM out (16384,256)
__device__ __align__(16) float g_h2[4194304];    // (1024,4096) fc A
__device__ __align__(16) float g_emb[524288];    // (1024,512)
__device__ __align__(16) float g_eo[3145728];    // (6,1024,512) expert raw out
__device__ __align__(16) int   g_topi[128];
__device__ __align__(16) float g_topw[128];
__device__ __align__(16) __nv_bfloat16 g_w1b_hi[16384],   g_w1b_lo[16384];    // [64][256]
__device__ __align__(16) __nv_bfloat16 g_w2b_hi[262144],  g_w2b_lo[262144];   // [256][1024]
__device__ __align__(16) __nv_bfloat16 g_fwb_hi[2097152], g_fwb_lo[2097152];  // [512][4096]
__device__ __align__(16) __nv_bfloat16 g_ewb_hi[1572864], g_ewb_lo[1572864];  // [6][512][512] n-major

// ============================ MMA helpers (validated) ============================
__device__ __forceinline__ uint32_t smem_u32(const void* p) {
    uint32_t a;
    asm("{ .reg .u64 t; cvta.to.shared.u64 t, %1; cvt.u32.u64 %0, t; }" : "=r"(a) : "l"(p));
    return a;
}
__device__ __forceinline__ void ldsm4(uint32_t r[4], uint32_t a) {
    asm volatile("ldmatrix.sync.aligned.m8n8.x4.shared.b16 {%0,%1,%2,%3}, [%4];"
                 : "=r"(r[0]), "=r"(r[1]), "=r"(r[2]), "=r"(r[3]) : "r"(a));
}
__device__ __forceinline__ void mma16816(float c[4], const uint32_t a[4], const uint32_t b[2]) {
    asm volatile(
        "mma.sync.aligned.m16n8k16.row.col.f32.bf16.bf16.f32 "
        "{%0,%1,%2,%3}, {%4,%5,%6,%7}, {%8,%9}, {%0,%1,%2,%3};"
        : "+f"(c[0]), "+f"(c[1]), "+f"(c[2]), "+f"(c[3])
        : "r"(a[0]), "r"(a[1]), "r"(a[2]), "r"(a[3]), "r"(b[0]), "r"(b[1]));
}
struct __align__(8)  BF4 { __nv_bfloat16 h[4]; };

__device__ __forceinline__ float gelu_exact(float y) {
    return 0.5f * y * (1.f + erff(y * 0.70710678118654752440f));
}
__device__ __forceinline__ void split4(const float4 v, BF4& hi, BF4& lo) {
    float f[4] = {v.x, v.y, v.z, v.w};
#pragma unroll
    for (int t = 0; t < 4; t++) {
        hi.h[t] = __float2bfloat16(f[t]);
        lo.h[t] = __float2bfloat16(f[t] - __bfloat162float(hi.h[t]));
    }
}

// warp tile 16x64, one BK=32 chunk, hi/lo split. SMEM rows 80B stride. (validated)
__device__ __forceinline__ void warp_mma16(
    uint32_t aHi, uint32_t aLo, uint32_t bHi, uint32_t bLo,
    int mrow0, int ncol0, int lane, float acc[8][4]) {
#pragma unroll
    for (int ks = 0; ks < 2; ks++) {
        const int k0 = ks * 16;
        uint32_t ah[4], al[4];
        {
            uint32_t ro = (uint32_t)((mrow0 + (lane & 15)) * 80 + (k0 + (lane >> 4) * 8) * 2);
            ldsm4(ah, aHi + ro);
            ldsm4(al, aLo + ro);
        }
        uint32_t bh[8][2], bl[8][2];
#pragma unroll
        for (int np = 0; np < 4; np++) {
            uint32_t ro = (uint32_t)((ncol0 + np * 16 + (lane & 7) + ((lane >> 4) * 8)) * 80 +
                                     (k0 + ((lane >> 3) & 1) * 8) * 2);
            uint32_t t[4];
            ldsm4(t, bHi + ro);
            bh[np * 2][0] = t[0]; bh[np * 2][1] = t[1];
            bh[np * 2 + 1][0] = t[2]; bh[np * 2 + 1][1] = t[3];
            ldsm4(t, bLo + ro);
            bl[np * 2][0] = t[0]; bl[np * 2][1] = t[1];
            bl[np * 2 + 1][0] = t[2]; bl[np * 2 + 1][1] = t[3];
        }
#pragma unroll
        for (int nf = 0; nf < 8; nf++) {
            mma16816(acc[nf], ah, bh[nf]);
            mma16816(acc[nf], ah, bl[nf]);
            mma16816(acc[nf], al, bh[nf]);
        }
    }
}

// ============================ weight prep ============================
__global__ __launch_bounds__(256) void prep_kernel(const float* __restrict__ w1,
                                                   const float* __restrict__ w2) {
    int idx = blockIdx.x * 256 + threadIdx.x;
    if (idx < 16384) {
        int n = idx >> 8, k = idx & 255;
        int kh = k >> 6, kw = (k >> 4) & 3, ci = k & 15;
        float v = w1[n * 256 + ci * 16 + kh * 4 + kw];
        __nv_bfloat16 h = __float2bfloat16(v);
        g_w1b_hi[idx] = h;
        g_w1b_lo[idx] = __float2bfloat16(v - __bfloat162float(h));
    }
    if (idx < 262144) {
        int n = idx >> 10, k = idx & 1023;
        int kh = k >> 8, kw = (k >> 6) & 3, ci = k & 63;
        float v = w2[n * 1024 + ci * 16 + kh * 4 + kw];
        __nv_bfloat16 h = __float2bfloat16(v);
        g_w2b_hi[idx] = h;
        g_w2b_lo[idx] = __float2bfloat16(v - __bfloat162float(h));
    }
}

// fc_w fp32 [4096][512] -> bf16 hi/lo [512][4096] (verbatim, validated)
__global__ __launch_bounds__(256) void transpose_cvt(const float* __restrict__ src) {
    __shared__ float tile[32][33];
    int c0 = blockIdx.x * 32, r0 = blockIdx.y * 32;
#pragma unroll
    for (int q = 0; q < 4; q++)
        tile[threadIdx.y + q * 8][threadIdx.x] =
            src[(size_t)(r0 + threadIdx.y + q * 8) * 512 + c0 + threadIdx.x];
    __syncthreads();
#pragma unroll
    for (int q = 0; q < 4; q++) {
        int c = c0 + threadIdx.y + q * 8;
        float v = tile[threadIdx.x][threadIdx.y + q * 8];
        __nv_bfloat16 h = __float2bfloat16(v);
        g_fwb_hi[(size_t)c * 4096 + r0 + threadIdx.x] = h;
        g_fwb_lo[(size_t)c * 4096 + r0 + threadIdx.x] =
            __float2bfloat16(v - __bfloat162float(h));
    }
}

// expert_w fp32 [6][512][512] -> bf16 hi/lo [6][512][512] transposed per expert
__global__ __launch_bounds__(256) void transpose_cvt_e(const float* __restrict__ src) {
    __shared__ float tile[32][33];
    int c0 = blockIdx.x * 32, r0 = blockIdx.y * 32;
    const float* s = src + (size_t)blockIdx.z * 262144;
    __nv_bfloat16* dhi = g_ewb_hi + (size_t)blockIdx.z * 262144;
    __nv_bfloat16* dlo = g_ewb_lo + (size_t)blockIdx.z * 262144;
#pragma unroll
    for (int q = 0; q < 4; q++)
        tile[threadIdx.y + q * 8][threadIdx.x] =
            s[(size_t)(r0 + threadIdx.y + q * 8) * 512 + c0 + threadIdx.x];
    __syncthreads();
#pragma unroll
    for (int q = 0; q < 4; q++) {
        int c = c0 + threadIdx.y + q * 8;
        float v = tile[threadIdx.x][threadIdx.y + q * 8];
        __nv_bfloat16 h = __float2bfloat16(v);
        dhi[(size_t)c * 512 + r0 + threadIdx.x] = h;
        dlo[(size_t)c * 512 + r0 + threadIdx.x] =
            __float2bfloat16(v - __bfloat162float(h));
    }
}

// ============================ conv1 (verbatim R12, pipelined) ============================
__global__ __launch_bounds__(256, 1) void conv1_mma(
    const float* __restrict__ x, const float* __restrict__ cb,
    const float* __restrict__ lg, const float* __restrict__ lb) {
    __shared__ __align__(16) char smem[33280];
    const uint32_t sb = smem_u32(smem);
    const int tid = threadIdx.x, lane = tid & 31, w = tid >> 5;
    const int m0 = blockIdx.x * 128;
    constexpr int A_HI = 0, A_LO = 10240, B_HI = 20480, B_LO = 25600;
    const int mrow0 = w * 16;

    float acc[8][4];
#pragma unroll
    for (int b = 0; b < 8; b++)
#pragma unroll
        for (int c = 0; c < 4; c++) acc[b][c] = 0.f;

    const int br = tid >> 2, bkp = tid & 3;
    float4 ra[4];
    uint4 rbh, rbl;

#pragma unroll
    for (int q = 0; q < 4; q++) {
        int idx = tid * 4 + q;
        int ml = idx >> 3, kp = idx & 7;
        int m = m0 + ml;
        int bt = m >> 8, ij = m & 255, i = ij >> 4, j = ij & 15;
        int k = kp * 4;
        int kh = k >> 6, ko = k & 63;
        ra[q] = *(const float4*)&x[(size_t)bt * 65536 + (4 * i + kh) * 1024 + j * 64 + ko];
    }
    rbh = *(const uint4*)&g_w1b_hi[br * 256 + bkp * 8];
    rbl = *(const uint4*)&g_w1b_lo[br * 256 + bkp * 8];

    for (int ch = 0; ch < 8; ch++) {
        __syncthreads();
#pragma unroll
        for (int q = 0; q < 4; q++) {
            int idx = tid * 4 + q;
            int ml = idx >> 3, kp = idx & 7;
            BF4 hi, lo;
            split4(ra[q], hi, lo);
            *(uint2*)(smem + A_HI + ml * 80 + kp * 8) = *(uint2*)&hi;
            *(uint2*)(smem + A_LO + ml * 80 + kp * 8) = *(uint2*)&lo;
        }
        *(uint4*)(smem + B_HI + br * 80 + bkp * 16) = rbh;
        *(uint4*)(smem + B_LO + br * 80 + bkp * 16) = rbl;
        if (ch < 7) {
            const int kc = (ch + 1) * 32;
#pragma unroll
            for (int q = 0; q < 4; q++) {
                int idx = tid * 4 + q;
                int ml = idx >> 3, kp = idx & 7;
                int m = m0 + ml;
                int bt = m >> 8, ij = m & 255, i = ij >> 4, j = ij & 15;
                int k = kc + kp * 4;
                int kh = k >> 6, ko = k & 63;
                ra[q] = *(const float4*)&x[(size_t)bt * 65536 + (4 * i + kh) * 1024 + j * 64 + ko];
            }
            rbh = *(const uint4*)&g_w1b_hi[br * 256 + kc + bkp * 8];
            rbl = *(const uint4*)&g_w1b_lo[br * 256 + kc + bkp * 8];
        }
        __syncthreads();
        warp_mma16(sb + A_HI, sb + A_LO, sb + B_HI, sb + B_LO, mrow0, 0, lane, acc);
    }
    __syncthreads();
    float* C = (float*)smem;  // [128][65]
    {
        int g = lane >> 2, t2 = (lane & 3) * 2;
#pragma unroll
        for (int nf = 0; nf < 8; nf++) {
            int c = nf * 8 + t2;
            C[(mrow0 + g) * 65 + c] = acc[nf][0];
            C[(mrow0 + g) * 65 + c + 1] = acc[nf][1];
            C[(mrow0 + g + 8) * 65 + c] = acc[nf][2];
            C[(mrow0 + g + 8) * 65 + c + 1] = acc[nf][3];
        }
    }
    __syncthreads();
    if (tid < 128) {
        float v[64];
        float s = 0.f, s2 = 0.f;
#pragma unroll
        for (int c = 0; c < 64; c++) {
            v[c] = C[tid * 65 + c] + cb[c];
            s += v[c]; s2 += v[c] * v[c];
        }
        float mean = s * (1.f / 64.f);
        float inv = rsqrtf(s2 * (1.f / 64.f) - mean * mean + 1e-5f);
        size_t base = (size_t)(m0 + tid) * 64;
#pragma unroll
        for (int g4 = 0; g4 < 16; g4++) {
            float4 o;
            float* po = &o.x;
#pragma unroll
            for (int t = 0; t < 4; t++) {
                int c = g4 * 4 + t;
                po[t] = gelu_exact((v[c] - mean) * inv * lg[c] + lb[c]);
            }
            *(float4*)&g_h1[base + g4 * 4] = o;
        }
    }
}

// ============================ pipelined BM=64 x BN=128 load helpers (verbatim R12) ============================
template <int MODE>
__device__ __forceinline__ void ldA2(const float* __restrict__ Af, size_t a_row0,
                                     size_t a_stride, int tid, int kc, float4 ra[2]) {
#pragma unroll
    for (int q = 0; q < 2; q++) {
        int idx = tid * 2 + q;
        int ml = idx >> 3, kp = idx & 7;
        if (MODE == 0) {
            ra[q] = *(const float4*)&Af[(a_row0 + ml) * a_stride + kc + kp * 4];
        } else {
            int m = (int)a_row0 + ml;
            int bt = m >> 4, ij = m & 15, oi = ij >> 2, oj = ij & 3;
            int k = kc + kp * 4;
            int kh = k >> 8, ko = k & 255;
            ra[q] = *(const float4*)&g_h1[(size_t)bt * 16384 + (4 * oi + kh) * 1024 + oj * 256 + ko];
        }
    }
}
__device__ __forceinline__ void ldB2(const __nv_bfloat16* __restrict__ Bhi,
                                     const __nv_bfloat16* __restrict__ Blo,
                                     size_t b_row0, size_t b_stride, int tid, int kc,
                                     uint4 rbh[2], uint4 rbl[2]) {
#pragma unroll
    for (int it = 0; it < 2; it++) {
        int idx = tid + it * 256;
        int r = idx >> 2, kp = idx & 3;
        size_t src = (b_row0 + r) * b_stride + kc + kp * 8;
        rbh[it] = *(const uint4*)&Bhi[src];
        rbl[it] = *(const uint4*)&Blo[src];
    }
}
__device__ __forceinline__ void stAB2(char* smem, int tid, const float4 ra[2],
                                      const uint4 rbh[2], const uint4 rbl[2]) {
    constexpr int A_HI = 0, A_LO = 5120, B_HI = 10240, B_LO = 20480;
#pragma unroll
    for (int q = 0; q < 2; q++) {
        int idx = tid * 2 + q;
        int ml = idx >> 3, kp = idx & 7;
        BF4 hi, lo;
        split4(ra[q], hi, lo);
        *(uint2*)(smem + A_HI + ml * 80 + kp * 8) = *(uint2*)&hi;
        *(uint2*)(smem + A_LO + ml * 80 + kp * 8) = *(uint2*)&lo;
    }
#pragma unroll
    for (int it = 0; it < 2; it++) {
        int idx = tid + it * 256;
        int r = idx >> 2, kp = idx & 3;
        *(uint4*)(smem + B_HI + r * 80 + kp * 16) = rbh[it];
        *(uint4*)(smem + B_LO + r * 80 + kp * 16) = rbl[it];
    }
}

template <int NCH, int MODE>
__device__ __forceinline__ void gemm64x128_pipe(
    char* smem, uint32_t sb, int tid, int lane, int mrow0, int ncol0,
    const float* __restrict__ Af, size_t a_row0, size_t a_stride,
    const __nv_bfloat16* __restrict__ Bhi, const __nv_bfloat16* __restrict__ Blo,
    size_t b_row0, size_t b_stride, float acc[8][4]) {
    constexpr int A_HI = 0, A_LO = 5120, B_HI = 10240, B_LO = 20480;
    float4 ra[2];
    uint4 rbh[2], rbl[2];
    ldA2<MODE>(Af, a_row0, a_stride, tid, 0, ra);
    ldB2(Bhi, Blo, b_row0, b_stride, tid, 0, rbh, rbl);
    for (int ch = 0; ch < NCH; ch++) {
        __syncthreads();
        stAB2(smem, tid, ra, rbh, rbl);
        if (ch + 1 < NCH) {
            ldA2<MODE>(Af, a_row0, a_stride, tid, (ch + 1) * 32, ra);
            ldB2(Bhi, Blo, b_row0, b_stride, tid, (ch + 1) * 32, rbh, rbl);
        }
        __syncthreads();
        warp_mma16(sb + A_HI, sb + A_LO, sb + B_HI, sb + B_LO, mrow0, ncol0, lane, acc);
    }
}

#define INIT_ACC8(acc) \
    _Pragma("unroll") for (int _b = 0; _b < 8; _b++) \
    _Pragma("unroll") for (int _c = 0; _c < 4; _c++) acc[_b][_c] = 0.f;

// ---- conv2: M=16384 K=1024 N=256 raw -> g_c2; grid (2,256); 2 CTAs/SM ----
__global__ __launch_bounds__(256, 2) void conv2_mma() {
    __shared__ __align__(16) char smem[30720];
    const uint32_t sb = smem_u32(smem);
    const int tid = threadIdx.x, lane = tid & 31, w = tid >> 5;
    const int n0 = blockIdx.x * 128, m0 = blockIdx.y * 64;
    const int mrow0 = (w >> 1) * 16, ncol0 = (w & 1) * 64;
    float acc[8][4];
    INIT_ACC8(acc);
    gemm64x128_pipe<32, 1>(smem, sb, tid, lane, mrow0, ncol0,
                           nullptr, (size_t)m0, 0,
                           g_w2b_hi, g_w2b_lo, (size_t)n0, 1024, acc);
    int g = lane >> 2, t2 = (lane & 3) * 2;
    int row = m0 + mrow0 + g;
#pragma unroll
    for (int nf = 0; nf < 8; nf++) {
        int col = n0 + ncol0 + nf * 8 + t2;
        *(float2*)&g_c2[(size_t)row * 256 + col] = make_float2(acc[nf][0], acc[nf][1]);
        *(float2*)&g_c2[(size_t)(row + 8) * 256 + col] = make_float2(acc[nf][2], acc[nf][3]);
    }
}

// ---- ln2 (verbatim, validated) ----
__global__ __launch_bounds__(256) void ln2_kernel(
    const float* __restrict__ cb, const float* __restrict__ lg, const float* __restrict__ lb) {
    const int lane = threadIdx.x & 31, w = threadIdx.x >> 5;
    const int row = blockIdx.x * 8 + w;
    const int c0 = lane * 8;
    float v[8];
    float4 a = *(const float4*)&g_c2[(size_t)row * 256 + c0];
    float4 b = *(const float4*)&g_c2[(size_t)row * 256 + c0 + 4];
    float4 ba = *(const float4*)&cb[c0];
    float4 bb = *(const float4*)&cb[c0 + 4];
    v[0] = a.x + ba.x; v[1] = a.y + ba.y; v[2] = a.z + ba.z; v[3] = a.w + ba.w;
    v[4] = b.x + bb.x; v[5] = b.y + bb.y; v[6] = b.z + bb.z; v[7] = b.w + bb.w;
    float s = 0.f, s2 = 0.f;
#pragma unroll
    for (int t = 0; t < 8; t++) { s += v[t]; s2 += v[t] * v[t]; }
#pragma unroll
    for (int d = 16; d > 0; d >>= 1) {
        s += __shfl_xor_sync(0xffffffff, s, d);
        s2 += __shfl_xor_sync(0xffffffff, s2, d);
    }
    float mean = s * (1.f / 256.f);
    float inv = rsqrtf(s2 * (1.f / 256.f) - mean * mean + 1e-5f);
    float4 lga = *(const float4*)&lg[c0];
    float4 lgb = *(const float4*)&lg[c0 + 4];
    float4 lba = *(const float4*)&lb[c0];
    float4 lbb = *(const float4*)&lb[c0 + 4];
    float gm[8] = {lga.x, lga.y, lga.z, lga.w, lgb.x, lgb.y, lgb.z, lgb.w};
    float bt[8] = {lba.x, lba.y, lba.z, lba.w, lbb.x, lbb.y, lbb.z, lbb.w};
    float4 o0, o1;
    float* p0 = &o0.x; float* p1 = &o1.x;
#pragma unroll
    for (int t = 0; t < 4; t++) p0[t] = gelu_exact((v[t] - mean) * inv * gm[t] + bt[t]);
#pragma unroll
    for (int t = 4; t < 8; t++) p1[t - 4] = gelu_exact((v[t] - mean) * inv * gm[t] + bt[t]);
    *(float4*)&g_h2[(size_t)row * 256 + c0] = o0;
    *(float4*)&g_h2[(size_t)row * 256 + c0 + 4] = o1;
}

// ---- fc (verbatim R12) ----
__global__ __launch_bounds__(256, 1) void fc_mma(const float* __restrict__ fb) {
    __shared__ __align__(16) char smem[30720];
    const uint32_t sb = smem_u32(smem);
    const int tid = threadIdx.x, lane = tid & 31, w = tid >> 5;
    const int n0 = blockIdx.x * 128, m0 = blockIdx.y * 64;
    const int mrow0 = (w >> 1) * 16, ncol0 = (w & 1) * 64;
    float acc[8][4];
    INIT_ACC8(acc);
    gemm64x128_pipe<128, 0>(smem, sb, tid, lane, mrow0, ncol0,
                            g_h2, (size_t)m0, 4096,
                            g_fwb_hi, g_fwb_lo, (size_t)n0, 4096, acc);
    int g = lane >> 2, t2 = (lane & 3) * 2;
    int row = m0 + mrow0 + g;
#pragma unroll
    for (int nf = 0; nf < 8; nf++) {
        int col = n0 + ncol0 + nf * 8 + t2;
        float2 b01 = *(const float2*)&fb[col];
        *(float2*)&g_emb[(size_t)row * 512 + col] =
            make_float2(acc[nf][0] + b01.x, acc[nf][1] + b01.y);
        *(float2*)&g_emb[(size_t)(row + 8) * 512 + col] =
            make_float2(acc[nf][2] + b01.x, acc[nf][3] + b01.y);
    }
}

// ---- experts dense via mma: per e, M=1024 K=512 N=512 raw -> g_eo; grid (4,16,6) ----
__global__ __launch_bounds__(256, 1) void expert_mma() {
    __shared__ __align__(16) char smem[30720];
    const uint32_t sb = smem_u32(smem);
    const int tid = threadIdx.x, lane = tid & 31, w = tid >> 5;
    const int n0 = blockIdx.x * 128, m0 = blockIdx.y * 64, e = blockIdx.z;
    const int mrow0 = (w >> 1) * 16, ncol0 = (w & 1) * 64;
    float acc[8][4];
    INIT_ACC8(acc);
    gemm64x128_pipe<16, 0>(smem, sb, tid, lane, mrow0, ncol0,
                           g_emb, (size_t)m0, 512,
                           g_ewb_hi + (size_t)e * 262144, g_ewb_lo + (size_t)e * 262144,
                           (size_t)n0, 512, acc);
    int g = lane >> 2, t2 = (lane & 3) * 2;
    size_t row = (size_t)e * 1024 + m0 + mrow0 + g;
#pragma unroll
    for (int nf = 0; nf < 8; nf++) {
        int col = n0 + ncol0 + nf * 8 + t2;
        *(float2*)&g_eo[row * 512 + col] = make_float2(acc[nf][0], acc[nf][1]);
        *(float2*)&g_eo[(row + 8) * 512 + col] = make_float2(acc[nf][2], acc[nf][3]);
    }
}

// ============================ Fourier gating (emits top-2) ============================
__global__ __launch_bounds__(128) void gate_kernel(const float* __restrict__ w_gate) {
    const int b = blockIdx.x;
    const int tid = threadIdx.x;
    __shared__ float cs[8][16], sn[8][16];
    __shared__ float lgs[6];
    {
        int f = tid >> 4, t = tid & 15;
        float ang = -6.28318530717958647692f * (float)(f + 1) * (float)t * (1.f / 16.f);
        cs[f][t] = cosf(ang);
        sn[f][t] = sinf(ang);
    }
    if (tid < 6) lgs[tid] = 0.f;
    __syncthreads();
    float part[6] = {0.f, 0.f, 0.f, 0.f, 0.f, 0.f};
    for (int d = tid; d < 512; d += 128) {
        float v[16];
#pragma unroll
        for (int t = 0; t < 16; t++) v[t] = g_emb[(b * 16 + t) * 512 + d];
#pragma unroll
        for (int f = 0; f < 8; f++) {
            float re = 0.f, im = 0.f;
#pragma unroll
            for (int t = 0; t < 16; t++) {
                re = fmaf(v[t], cs[f][t], re);
                im = fmaf(v[t], sn[f][t], im);
            }
            float amp = sqrtf(re * re + im * im) * 0.25f;
#pragma unroll
            for (int e = 0; e < 6; e++) part[e] = fmaf(amp, w_gate[f * 6 + e], part[e]);
        }
    }
#pragma unroll
    for (int e = 0; e < 6; e++) atomicAdd(&lgs[e], part[e]);
    __syncthreads();
    if (tid == 0) {
        float wv[6];
#pragma unroll
        for (int e = 0; e < 6; e++) wv[e] = lgs[e] * (1.f / 512.f);
        int i1 = 0;
        for (int e = 1; e < 6; e++) if (wv[e] > wv[i1]) i1 = e;
        int i2 = -1;
        for (int e = 0; e < 6; e++) {
            if (e == i1) continue;
            if (i2 < 0 || wv[e] > wv[i2]) i2 = e;
        }
        float e2 = expf(wv[i2] - wv[i1]);
        float s = 1.f + e2;
        g_topi[b * 2] = i1; g_topi[b * 2 + 1] = i2;
        g_topw[b * 2] = 1.f / s; g_topw[b * 2 + 1] = e2 / s;
    }
}

// ============================ combine ============================
__global__ __launch_bounds__(256) void combine_kernel(const float* __restrict__ eb,
                                                      float* __restrict__ out) {
    int t = blockIdx.x * 256 + threadIdx.x;  // 131072
    int mr = t >> 7, c4 = (t & 127) * 4;
    int b = mr >> 4;
    int i1 = g_topi[b * 2], i2 = g_topi[b * 2 + 1];
    float w1 = g_topw[b * 2], w2 = g_topw[b * 2 + 1];
    float4 a = *(const float4*)&g_eo[((size_t)i1 * 1024 + mr) * 512 + c4];
    float4 c = *(const float4*)&g_eo[((size_t)i2 * 1024 + mr) * 512 + c4];
    float4 b1 = *(const float4*)&eb[i1 * 512 + c4];
    float4 b2 = *(const float4*)&eb[i2 * 512 + c4];
    float4 o;
    o.x = w1 * expf(a.x + b1.x) + w2 * expf(c.x + b2.x);
    o.y = w1 * expf(a.y + b1.y) + w2 * expf(c.y + b2.y);
    o.z = w1 * expf(a.z + b1.z) + w2 * expf(c.z + b2.z);
    o.w = w1 * expf(a.w + b1.w) + w2 * expf(c.w + b2.w);
    o.x = logf(o.x == 0.f ? 2.220446049250313e-16f : o.x);
    o.y = logf(o.y == 0.f ? 2.220446049250313e-16f : o.y);
    o.z = logf(o.z == 0.f ? 2.220446049250313e-16f : o.z);
    o.w = logf(o.w == 0.f ? 2.220446049250313e-16f : o.w);
    *(float4*)&out[(size_t)mr * 512 + c4] = o;
}

// ============================ launch ============================
extern "C" void kernel_launch(void* const* d_in, const int* in_sizes, int n_in,
                              void* d_out, int out_size) {
    const float* x       = (const float*)d_in[0];
    const float* conv1_w = (const float*)d_in[1];
    const float* conv1_b = (const float*)d_in[2];
    const float* ln1_g   = (const float*)d_in[3];
    const float* ln1_b   = (const float*)d_in[4];
    const float* conv2_w = (const float*)d_in[5];
    const float* conv2_b = (const float*)d_in[6];
    const float* ln2_g   = (const float*)d_in[7];
    const float* ln2_b   = (const float*)d_in[8];
    const float* fc_w    = (const float*)d_in[9];
    const float* fc_b    = (const float*)d_in[10];
    const float* w_gate  = (const float*)d_in[11];
    const float* exp_w   = (const float*)d_in[12];
    const float* exp_b   = (const float*)d_in[13];
    float* out = (float*)d_out;

    prep_kernel<<<1024, 256>>>(conv1_w, conv2_w);
    transpose_cvt<<<dim3(16, 128), dim3(32, 8)>>>(fc_w);
    transpose_cvt_e<<<dim3(16, 16, 6), dim3(32, 8)>>>(exp_w);
    conv1_mma<<<2048, 256>>>(x, conv1_b, ln1_g, ln1_b);
    conv2_mma<<<dim3(2, 256), 256>>>();
    ln2_kernel<<<2048, 256>>>(conv2_b, ln2_g, ln2_b);
    fc_mma<<<dim3(4, 16), 256>>>(fc_b);
    gate_kernel<<<64, 128>>>(w_gate);
    expert_mma<<<dim3(4, 16, 6), 256>>>();
    combine_kernel<<<512, 256>>>(exp_b, out);
}